// round 5
// baseline (speedup 1.0000x reference)
#include <cuda_runtime.h>
#include <cuda_bf16.h>
#include <math.h>
#include <stdint.h>

// ---------------- problem constants ----------------
#define VOCAB   10000
#define D_GNN   64
#define L_TOK   8
#define DG      256
#define NH      4
#define HD      64
#define N_NODES 8192
#define N_EDGES 2048
#define FD      512
#define ROWS    16384
#define NTMAX   80

// ---------------- scratch (static device memory) ----------------
__device__ float g_x   [N_NODES * FD];
__device__ float g_e   [N_EDGES * FD];
__device__ float g_msg [N_EDGES * FD];
__device__ float g_agg [N_NODES * FD];
__device__ float g_h   [N_NODES * FD];
__device__ float g_eh  [N_EDGES * FD];
__device__ float g_zg  [ROWS * DG];
__device__ float g_qkv [ROWS * 3 * DG];
__device__ float g_wqkv[DG * 3 * DG];
__device__ float g_ao  [ROWS * DG];
__device__ float g_x1  [ROWS * DG];
__device__ float g_ffn [ROWS * 4 * DG];
__device__ float g_x2  [ROWS * DG];
__device__ float g_y   [ROWS * D_GNN];
__device__ float g_embT[D_GNN * VOCAB];
__device__ int   g_mtok[N_EDGES * L_TOK];
__device__ float2 g_tstat[ROWS * NTMAX];
__device__ float g_rmax[ROWS];
__device__ float g_rinv[ROWS];
__device__ int   g_mask_mode;

// ---------------- mask dtype detection ----------------
__global__ void detect_mask_kernel(const int* __restrict__ mr) {
    __shared__ int notint, notflt;
    if (threadIdx.x == 0) { notint = 0; notflt = 0; }
    __syncthreads();
    int w = mr[threadIdx.x];
    if (w != 0 && w != 1)          atomicExch(&notint, 1);
    if (w != 0 && w != 0x3F800000) atomicExch(&notflt, 1);
    __syncthreads();
    if (threadIdx.x == 0)
        g_mask_mode = notint ? (notflt ? 2 : 1) : 0;
}

__global__ void mask_kernel(const int* __restrict__ etok, const void* __restrict__ maskraw,
                            float* labels_out) {
    int i = blockIdx.x * blockDim.x + threadIdx.x;
    if (i >= N_EDGES * L_TOK) return;
    int e = i >> 3;
    int t = etok[i];
    bool mr;
    int mode = g_mask_mode;
    if (mode == 0)      mr = ((const int*)maskraw)[e] != 0;
    else if (mode == 1) mr = ((const float*)maskraw)[e] != 0.0f;
    else                mr = ((const unsigned char*)maskraw)[e] != 0;
    bool msk = mr && (t >= 4);
    g_mtok[i] = msk ? 4 : t;
    if (labels_out) labels_out[i] = msk ? (float)t : -100.0f;
}

__global__ void embed_kernel(const int* __restrict__ tok, const float* __restrict__ emb,
                             float4* __restrict__ out, int total4) {
    int i = blockIdx.x * blockDim.x + threadIdx.x;
    if (i >= total4) return;
    int ti = i >> 4;
    int d4 = i & 15;
    out[i] = *(const float4*)(emb + tok[ti] * 64 + d4 * 4);
}

__global__ void transpose_emb_kernel(const float* __restrict__ emb) {
    int i = blockIdx.x * blockDim.x + threadIdx.x;
    if (i >= D_GNN * VOCAB) return;
    int k = i / VOCAB, v = i - k * VOCAB;
    g_embT[i] = emb[v * 64 + k];
}

__global__ void pack_qkv_kernel(const float* __restrict__ Wq, const float* __restrict__ Wk,
                                const float* __restrict__ Wv) {
    int i = blockIdx.x * blockDim.x + threadIdx.x;
    if (i >= DG * DG) return;
    int k = i >> 8, n = i & 255;
    g_wqkv[k * 768 + n]       = Wq[i];
    g_wqkv[k * 768 + 256 + n] = Wk[i];
    g_wqkv[k * 768 + 512 + n] = Wv[i];
}

__global__ void zero_kernel(float4* __restrict__ p, int n4) {
    int i = blockIdx.x * blockDim.x + threadIdx.x;
    if (i < n4) p[i] = make_float4(0.f, 0.f, 0.f, 0.f);
}

__global__ void scatter_add_kernel(const int* __restrict__ dst) {
    int i = blockIdx.x * blockDim.x + threadIdx.x;
    if (i >= N_EDGES * FD / 4) return;
    int e = i >> 7, c4 = i & 127;
    float4 v = *(const float4*)(g_msg + ((size_t)e << 9) + c4 * 4);
    float* base = g_agg + (size_t)dst[e] * FD + c4 * 4;
    atomicAdd(base + 0, v.x);
    atomicAdd(base + 1, v.y);
    atomicAdd(base + 2, v.z);
    atomicAdd(base + 3, v.w);
}

__global__ void edge_gather_kernel(const int* __restrict__ src, const int* __restrict__ dst) {
    int i = blockIdx.x * blockDim.x + threadIdx.x;
    if (i >= N_EDGES * FD / 4) return;
    int e = i >> 7, c4 = i & 127;
    const float4* s = (const float4*)(g_h + (size_t)src[e] * FD) + c4;
    const float4* d = (const float4*)(g_h + (size_t)dst[e] * FD) + c4;
    float4 a = *s, b = *d;
    a.x += b.x; a.y += b.y; a.z += b.z; a.w += b.w;
    *((float4*)(g_eh + ((size_t)e << 9)) + c4) = a;
}

// ---------------- tf32 tensor-core GEMM, 3-stage cp.async, warp tile 64x64 ----------------
// EPI: 0 plain | 1 +bias[n] | 2 relu(+extra[m*ld+n]) | 3 relu(+extra[gidx[m]*ld+n])
//      4 +extra[m*ld+n] | 5 gelu | 7 stats-only | 8 softmax-write

__device__ __forceinline__ void mma_tf32(float c[4], const uint32_t a[4], const uint32_t b[2]) {
    asm volatile(
        "mma.sync.aligned.m16n8k8.row.col.f32.tf32.tf32.f32 "
        "{%0,%1,%2,%3}, {%4,%5,%6,%7}, {%8,%9}, {%0,%1,%2,%3};"
        : "+f"(c[0]), "+f"(c[1]), "+f"(c[2]), "+f"(c[3])
        : "r"(a[0]), "r"(a[1]), "r"(a[2]), "r"(a[3]), "r"(b[0]), "r"(b[1]));
}

__device__ __forceinline__ void cp_async16(uint32_t dst, const void* src, bool pred) {
    int sz = pred ? 16 : 0;
    asm volatile("cp.async.cg.shared.global [%0], [%1], 16, %2;\n"
                 :: "r"(dst), "l"(src), "r"(sz));
}
__device__ __forceinline__ void cp_commit() {
    asm volatile("cp.async.commit_group;\n");
}
__device__ __forceinline__ void cp_wait0() {
    asm volatile("cp.async.wait_group 0;\n");
}
__device__ __forceinline__ void cp_wait1() {
    asm volatile("cp.async.wait_group 1;\n");
}

#define TBM 128
#define TBN 256
#define TBK 16
#define ASTR 20     // As[m][k] stride: banks (20g+tig)%32 all distinct
#define BSTR 264    // Bs[k][n] stride: banks (g + 8*tig)%32 all distinct
#define NSTAGE 3
#define SMEM_A_FLOATS (NSTAGE * TBM * ASTR)           // 7680
#define SMEM_B_FLOATS (NSTAGE * TBK * BSTR)           // 12672
#define GEMM_SMEM_BYTES ((SMEM_A_FLOATS + SMEM_B_FLOATS) * 4)

template<int EPI>
__global__ void __launch_bounds__(256)
tmma_k(const float* __restrict__ A, const float* __restrict__ B, float* __restrict__ C,
       int M, int N, int K,
       const float* __restrict__ extra, const int* __restrict__ gidx, int ldex,
       float2* __restrict__ tstat) {
    extern __shared__ float smem[];
    float (*As)[TBM][ASTR] = (float(*)[TBM][ASTR])smem;
    float (*Bs)[TBK][BSTR] = (float(*)[TBK][BSTR])(smem + SMEM_A_FLOATS);
    float2 (*sstat)[4] = (float2(*)[4])smem;   // alias over As, used post-mainloop

    int tid  = threadIdx.x;
    int lane = tid & 31;
    int warp = tid >> 5;
    int wm = warp & 1;           // 2 row groups of 64
    int wn = warp >> 1;          // 4 col groups of 64
    int g   = lane >> 2;
    int tig = lane & 3;
    int m0 = blockIdx.y * TBM;
    int n0 = blockIdx.x * TBN;

    float acc[4][8][4] = {};

    // load slots: A 2 chunks, B 4 chunks per thread
    int am[2], aq[2], bk[4], bn[4];
    #pragma unroll
    for (int i = 0; i < 2; i++) {
        int slot = tid + i * 256;
        am[i] = slot >> 2;            // 0..127
        aq[i] = (slot & 3) << 2;      // 0,4,8,12
    }
    #pragma unroll
    for (int i = 0; i < 4; i++) {
        int slot = tid + i * 256;
        bk[i] = slot >> 6;            // 0..15
        bn[i] = (slot & 63) << 2;     // 0..252
    }

    auto issue_load = [&](int s, int k0) {
        #pragma unroll
        for (int i = 0; i < 2; i++) {
            uint32_t da = (uint32_t)__cvta_generic_to_shared(&As[s][am[i]][aq[i]]);
            cp_async16(da, A + (size_t)(m0 + am[i]) * K + k0 + aq[i], true);
        }
        #pragma unroll
        for (int i = 0; i < 4; i++) {
            int gn = n0 + bn[i];
            uint32_t db = (uint32_t)__cvta_generic_to_shared(&Bs[s][bk[i]][bn[i]]);
            cp_async16(db, B + (size_t)(k0 + bk[i]) * N + gn, gn < N);
        }
    };

    int niter = K / TBK;   // >= 4 for all our shapes
    issue_load(0, 0);
    cp_commit();
    issue_load(1, TBK);
    cp_commit();

    for (int it = 0; it < niter; it++) {
        if (it == niter - 1) cp_wait0(); else cp_wait1();
        __syncthreads();
        if (it + 2 < niter) {
            issue_load((it + 2) % NSTAGE, (it + 2) * TBK);
            cp_commit();
        }
        int s = it % NSTAGE;
        #pragma unroll
        for (int ks = 0; ks < TBK; ks += 8) {
            uint32_t af[4][4], bf[8][2];
            #pragma unroll
            for (int mt = 0; mt < 4; mt++) {
                int rm = wm * 64 + mt * 16 + g;
                af[mt][0] = __float_as_uint(As[s][rm    ][ks + tig    ]);
                af[mt][1] = __float_as_uint(As[s][rm + 8][ks + tig    ]);
                af[mt][2] = __float_as_uint(As[s][rm    ][ks + tig + 4]);
                af[mt][3] = __float_as_uint(As[s][rm + 8][ks + tig + 4]);
            }
            #pragma unroll
            for (int nt = 0; nt < 8; nt++) {
                int cn = wn * 64 + nt * 8 + g;
                bf[nt][0] = __float_as_uint(Bs[s][ks + tig    ][cn]);
                bf[nt][1] = __float_as_uint(Bs[s][ks + tig + 4][cn]);
            }
            #pragma unroll
            for (int mt = 0; mt < 4; mt++)
                #pragma unroll
                for (int nt = 0; nt < 8; nt++)
                    mma_tf32(acc[mt][nt], af[mt], bf[nt]);
        }
    }

    if (EPI == 7) __syncthreads();   // allow sstat alias over As

    // ---------------- epilogue ----------------
    #pragma unroll
    for (int mt = 0; mt < 4; mt++) {
        #pragma unroll
        for (int half = 0; half < 2; half++) {
            int rib = wm * 64 + mt * 16 + half * 8 + g;
            int r = m0 + rib;
            int ebase = 0;
            if (EPI == 2 || EPI == 4) ebase = r * ldex;
            if (EPI == 3)             ebase = gidx[r] * ldex;
            float rmaxv = 0.0f, rinvv = 0.0f;
            if (EPI == 8) { rmaxv = g_rmax[r]; rinvv = g_rinv[r]; }

            float rmx = -1e30f, rsm = 0.0f;
            float vals[16];
            #pragma unroll
            for (int nt = 0; nt < 8; nt++) {
                int n = n0 + wn * 64 + nt * 8 + 2 * tig;
                float c0 = acc[mt][nt][half * 2 + 0];
                float c1 = acc[mt][nt][half * 2 + 1];
                if (EPI == 1) { c0 += extra[n]; c1 += extra[n + 1]; }
                else if (EPI == 2 || EPI == 3) {
                    c0 = fmaxf(c0 + extra[ebase + n],     0.0f);
                    c1 = fmaxf(c1 + extra[ebase + n + 1], 0.0f);
                } else if (EPI == 4) {
                    c0 += extra[ebase + n]; c1 += extra[ebase + n + 1];
                } else if (EPI == 5) {
                    float x = c0;
                    c0 = 0.5f * x * (1.0f + tanhf(0.7978845608028654f * (x + 0.044715f * x * x * x)));
                    x = c1;
                    c1 = 0.5f * x * (1.0f + tanhf(0.7978845608028654f * (x + 0.044715f * x * x * x)));
                }
                if (EPI == 7) {
                    vals[nt * 2 + 0] = (n     < N) ? c0 : -1e30f;
                    vals[nt * 2 + 1] = (n + 1 < N) ? c1 : -1e30f;
                    rmx = fmaxf(rmx, fmaxf(vals[nt * 2], vals[nt * 2 + 1]));
                } else if (EPI == 8) {
                    if (n < N) {
                        float p0 = __expf(c0 - rmaxv) * rinvv;
                        float p1 = __expf(c1 - rmaxv) * rinvv;
                        *(float2*)&C[(size_t)r * N + n] = make_float2(p0, p1);
                    }
                } else {
                    if (n + 1 < N) {
                        *(float2*)&C[(size_t)r * N + n] = make_float2(c0, c1);
                    } else if (n < N) {
                        C[(size_t)r * N + n] = c0;
                    }
                }
            }

            if (EPI == 7) {
                #pragma unroll
                for (int j = 0; j < 16; j++) rsm += __expf(vals[j] - rmx);
                #pragma unroll
                for (int off = 1; off <= 2; off <<= 1) {
                    float om = __shfl_xor_sync(0xffffffffu, rmx, off);
                    float os = __shfl_xor_sync(0xffffffffu, rsm, off);
                    float nm = fmaxf(rmx, om);
                    rsm = rsm * __expf(rmx - nm) + os * __expf(om - nm);
                    rmx = nm;
                }
                if (tig == 0) sstat[rib][wn] = make_float2(rmx, rsm);
            }
        }
    }

    if (EPI == 7) {
        __syncthreads();
        if (tid < TBM) {
            float m = -1e30f, ssum = 0.0f;
            #pragma unroll
            for (int w = 0; w < 4; w++) {
                float2 p = sstat[tid][w];
                float nm = fmaxf(m, p.x);
                ssum = ssum * __expf(m - nm) + p.y * __expf(p.x - nm);
                m = nm;
            }
            tstat[(size_t)(m0 + tid) * gridDim.x + blockIdx.x] = make_float2(m, ssum);
        }
    }
}

// ---------------- softmax stat combine ----------------
__global__ void combine_stats_kernel(int ntile) {
    int row = blockIdx.x * blockDim.x + threadIdx.x;
    if (row >= ROWS) return;
    float m = -1e30f, s = 0.0f;
    for (int t = 0; t < ntile; t++) {
        float2 p = g_tstat[(size_t)row * ntile + t];
        float nm = fmaxf(m, p.x);
        s = s * __expf(m - nm) + p.y * __expf(p.x - nm);
        m = nm;
    }
    g_rmax[row] = m;
    g_rinv[row] = 1.0f / s;
}

// ---------------- attention ----------------
__global__ void __launch_bounds__(256) attention_kernel() {
    __shared__ float qs[8][DG], ks[8][DG], vs[8][DG];
    int b = blockIdx.x;
    int tid = threadIdx.x;
    for (int i = tid; i < 8 * DG; i += 256) {
        int s = i >> 8, c = i & 255;
        size_t off = (size_t)(b * 8 + s) * 768 + c;
        qs[s][c] = g_qkv[off];
        ks[s][c] = g_qkv[off + 256];
        vs[s][c] = g_qkv[off + 512];
    }
    __syncthreads();

    int h  = tid >> 6;
    int qx = (tid >> 3) & 7;
    int kx = tid & 7;
    float att = 0.0f;
    #pragma unroll
    for (int d = 0; d < HD; d++)
        att += qs[qx][h * HD + d] * ks[kx][h * HD + d];
    att *= 0.125f;

    float mx = att;
    mx = fmaxf(mx, __shfl_xor_sync(0xffffffffu, mx, 4));
    mx = fmaxf(mx, __shfl_xor_sync(0xffffffffu, mx, 2));
    mx = fmaxf(mx, __shfl_xor_sync(0xffffffffu, mx, 1));
    float ex = expf(att - mx);
    float sm = ex;
    sm += __shfl_xor_sync(0xffffffffu, sm, 4);
    sm += __shfl_xor_sync(0xffffffffu, sm, 2);
    sm += __shfl_xor_sync(0xffffffffu, sm, 1);
    float a = ex / sm;

    int lane = tid & 31;
    int base = lane & ~7;
    float a_all[8];
    #pragma unroll
    for (int kk = 0; kk < 8; kk++)
        a_all[kk] = __shfl_sync(0xffffffffu, a, base + kk);

    #pragma unroll
    for (int t2 = 0; t2 < 8; t2++) {
        int d = kx * 8 + t2;
        float o = 0.0f;
        #pragma unroll
        for (int kk = 0; kk < 8; kk++)
            o += a_all[kk] * vs[kk][h * HD + d];
        g_ao[(size_t)(b * 8 + qx) * DG + h * HD + d] = o;
    }
}

// ---------------- host launcher ----------------
template<int EPI>
static void launch_one(const float* A, const float* B, float* C, int M, int N, int K,
                       const float* extra, const int* gidx, int ldex, float2* tstat) {
    static bool attr_done = false;
    if (!attr_done) {
        cudaFuncSetAttribute(tmma_k<EPI>, cudaFuncAttributeMaxDynamicSharedMemorySize,
                             GEMM_SMEM_BYTES);
        attr_done = true;
    }
    dim3 grid((N + TBN - 1) / TBN, M / TBM), blk(256);
    tmma_k<EPI><<<grid, blk, GEMM_SMEM_BYTES>>>(A, B, C, M, N, K, extra, gidx, ldex, tstat);
}

static void launch_gemm(int epi, const float* A, const float* B, float* C,
                        int M, int N, int K,
                        const float* extra = nullptr, const int* gidx = nullptr, int ldex = 0,
                        float2* tstat = nullptr) {
    switch (epi) {
        case 0: launch_one<0>(A, B, C, M, N, K, extra, gidx, ldex, tstat); break;
        case 1: launch_one<1>(A, B, C, M, N, K, extra, gidx, ldex, tstat); break;
        case 2: launch_one<2>(A, B, C, M, N, K, extra, gidx, ldex, tstat); break;
        case 3: launch_one<3>(A, B, C, M, N, K, extra, gidx, ldex, tstat); break;
        case 4: launch_one<4>(A, B, C, M, N, K, extra, gidx, ldex, tstat); break;
        case 5: launch_one<5>(A, B, C, M, N, K, extra, gidx, ldex, tstat); break;
        case 7: launch_one<7>(A, B, C, M, N, K, extra, gidx, ldex, tstat); break;
        case 8: launch_one<8>(A, B, C, M, N, K, extra, gidx, ldex, tstat); break;
    }
}

template <typename T>
static T* sym_addr(const void* sym) {
    void* p = nullptr;
    cudaGetSymbolAddress(&p, sym);
    return (T*)p;
}

extern "C" void kernel_launch(void* const* d_in, const int* in_sizes, int n_in,
                              void* d_out, int out_size) {
    const int*   node_tokens = (const int*)d_in[0];
    const int*   edge_tokens = (const int*)d_in[1];
    const int*   edge_index  = (const int*)d_in[2];
    const void*  mask_rows   = d_in[3];
    const float* emb    = (const float*)d_in[4];
    const float* W_msg  = (const float*)d_in[5];
    const float* W_node = (const float*)d_in[6];
    const float* lc1_w  = (const float*)d_in[7];
    const float* lc1_b  = (const float*)d_in[8];
    const float* lc2_w  = (const float*)d_in[9];
    const float* lc2_b  = (const float*)d_in[10];
    const float* Wq  = (const float*)d_in[11];
    const float* Wk  = (const float*)d_in[12];
    const float* Wv  = (const float*)d_in[13];
    const float* Wo  = (const float*)d_in[14];
    const float* Wf1 = (const float*)d_in[15];
    const float* Wf2 = (const float*)d_in[16];

    float* out = (float*)d_out;
    bool concat = (out_size != ROWS * VOCAB);
    float* labels_out = concat ? out : nullptr;
    float* probs      = concat ? out + ROWS : out;

    const int* src = edge_index;
    const int* dst = edge_index + N_EDGES;

    float* px   = sym_addr<float>(g_x);
    float* pe   = sym_addr<float>(g_e);
    float* pmsg = sym_addr<float>(g_msg);
    float* pagg = sym_addr<float>(g_agg);
    float* ph   = sym_addr<float>(g_h);
    float* peh  = sym_addr<float>(g_eh);
    float* pzg  = sym_addr<float>(g_zg);
    float* pqkv = sym_addr<float>(g_qkv);
    float* pwqkv= sym_addr<float>(g_wqkv);
    float* pao  = sym_addr<float>(g_ao);
    float* px1  = sym_addr<float>(g_x1);
    float* pffn = sym_addr<float>(g_ffn);
    float* px2  = sym_addr<float>(g_x2);
    float* py   = sym_addr<float>(g_y);
    float* pembT= sym_addr<float>(g_embT);
    int*   pmt  = sym_addr<int>(g_mtok);
    float2* pst = sym_addr<float2>(g_tstat);

    // 1. mask dtype detect + labels/masked tokens
    detect_mask_kernel<<<1, 512>>>((const int*)mask_rows);
    mask_kernel<<<(N_EDGES * L_TOK + 255) / 256, 256>>>(edge_tokens, mask_rows, labels_out);

    // 2. embeddings + weight packing
    embed_kernel<<<(N_NODES * FD / 4 + 255) / 256, 256>>>(node_tokens, emb, (float4*)px, N_NODES * FD / 4);
    embed_kernel<<<(N_EDGES * FD / 4 + 255) / 256, 256>>>(pmt, emb, (float4*)pe, N_EDGES * FD / 4);
    transpose_emb_kernel<<<(D_GNN * VOCAB + 255) / 256, 256>>>(emb);
    pack_qkv_kernel<<<(DG * DG + 255) / 256, 256>>>(Wq, Wk, Wv);

    // 3. GNN
    launch_gemm(3, pe, W_msg, pmsg, N_EDGES, FD, FD, px, src, FD);
    zero_kernel<<<(N_NODES * FD / 4 + 255) / 256, 256>>>((float4*)pagg, N_NODES * FD / 4);
    scatter_add_kernel<<<(N_EDGES * FD / 4 + 255) / 256, 256>>>(dst);
    launch_gemm(2, px, W_node, ph, N_NODES, FD, FD, pagg, nullptr, FD);
    edge_gather_kernel<<<(N_EDGES * FD / 4 + 255) / 256, 256>>>(src, dst);

    // 4. lc1
    launch_gemm(1, peh, lc1_w, pzg, ROWS, DG, D_GNN, lc1_b);

    // 5. transformer
    launch_gemm(0, pzg, pwqkv, pqkv, ROWS, 3 * DG, DG);
    attention_kernel<<<N_EDGES, 256>>>();
    launch_gemm(4, pao, Wo, px1, ROWS, DG, DG, pzg, nullptr, DG);
    launch_gemm(5, px1, Wf1, pffn, ROWS, 4 * DG, DG);
    launch_gemm(4, pffn, Wf2, px2, ROWS, DG, 4 * DG, px1, nullptr, DG);

    // 6. lc2 + two-pass LM head
    launch_gemm(1, px2, lc2_w, py, ROWS, D_GNN, DG, lc2_b);
    launch_gemm(7, py, pembT, probs, ROWS, VOCAB, D_GNN, nullptr, nullptr, 0, pst);
    int ntile = (VOCAB + TBN - 1) / TBN;
    combine_stats_kernel<<<(ROWS + 255) / 256, 256>>>(ntile);
    launch_gemm(8, py, pembT, probs, ROWS, VOCAB, D_GNN, nullptr, nullptr, 0, pst);
}

// round 6
// speedup vs baseline: 1.2077x; 1.2077x over previous
#include <cuda_runtime.h>
#include <cuda_bf16.h>
#include <math.h>
#include <stdint.h>

// ---------------- problem constants ----------------
#define VOCAB   10000
#define D_GNN   64
#define L_TOK   8
#define DG      256
#define NH      4
#define HD      64
#define N_NODES 8192
#define N_EDGES 2048
#define FD      512
#define ROWS    16384
#define NTMAX   80

// ---------------- scratch (static device memory) ----------------
__device__ float g_x   [N_NODES * FD];
__device__ float g_e   [N_EDGES * FD];
__device__ float g_msg [N_EDGES * FD];
__device__ float g_agg [N_NODES * FD];
__device__ float g_h   [N_NODES * FD];
__device__ float g_eh  [N_EDGES * FD];
__device__ float g_zg  [ROWS * DG];
__device__ float g_qkv [ROWS * 3 * DG];
__device__ float g_wqkv[DG * 3 * DG];
__device__ float g_ao  [ROWS * DG];
__device__ float g_x1  [ROWS * DG];
__device__ float g_ffn [ROWS * 4 * DG];
__device__ float g_x2  [ROWS * DG];
__device__ float g_y   [ROWS * D_GNN];
__device__ float g_embT[D_GNN * VOCAB];
__device__ int   g_mtok[N_EDGES * L_TOK];
__device__ float2 g_tstat[ROWS * NTMAX];
__device__ float g_rmax[ROWS];
__device__ float g_rinv[ROWS];
__device__ int   g_mask_mode;

// ---------------- mask dtype detection ----------------
__global__ void detect_mask_kernel(const int* __restrict__ mr) {
    __shared__ int notint, notflt;
    if (threadIdx.x == 0) { notint = 0; notflt = 0; }
    __syncthreads();
    int w = mr[threadIdx.x];
    if (w != 0 && w != 1)          atomicExch(&notint, 1);
    if (w != 0 && w != 0x3F800000) atomicExch(&notflt, 1);
    __syncthreads();
    if (threadIdx.x == 0)
        g_mask_mode = notint ? (notflt ? 2 : 1) : 0;
}

__global__ void mask_kernel(const int* __restrict__ etok, const void* __restrict__ maskraw,
                            float* labels_out) {
    int i = blockIdx.x * blockDim.x + threadIdx.x;
    if (i >= N_EDGES * L_TOK) return;
    int e = i >> 3;
    int t = etok[i];
    bool mr;
    int mode = g_mask_mode;
    if (mode == 0)      mr = ((const int*)maskraw)[e] != 0;
    else if (mode == 1) mr = ((const float*)maskraw)[e] != 0.0f;
    else                mr = ((const unsigned char*)maskraw)[e] != 0;
    bool msk = mr && (t >= 4);
    g_mtok[i] = msk ? 4 : t;
    if (labels_out) labels_out[i] = msk ? (float)t : -100.0f;
}

__global__ void embed_kernel(const int* __restrict__ tok, const float* __restrict__ emb,
                             float4* __restrict__ out, int total4) {
    int i = blockIdx.x * blockDim.x + threadIdx.x;
    if (i >= total4) return;
    int ti = i >> 4;
    int d4 = i & 15;
    out[i] = *(const float4*)(emb + tok[ti] * 64 + d4 * 4);
}

__global__ void transpose_emb_kernel(const float* __restrict__ emb) {
    int i = blockIdx.x * blockDim.x + threadIdx.x;
    if (i >= D_GNN * VOCAB) return;
    int k = i / VOCAB, v = i - k * VOCAB;
    g_embT[i] = emb[v * 64 + k];
}

__global__ void pack_qkv_kernel(const float* __restrict__ Wq, const float* __restrict__ Wk,
                                const float* __restrict__ Wv) {
    int i = blockIdx.x * blockDim.x + threadIdx.x;
    if (i >= DG * DG) return;
    int k = i >> 8, n = i & 255;
    g_wqkv[k * 768 + n]       = Wq[i];
    g_wqkv[k * 768 + 256 + n] = Wk[i];
    g_wqkv[k * 768 + 512 + n] = Wv[i];
}

__global__ void zero_kernel(float4* __restrict__ p, int n4) {
    int i = blockIdx.x * blockDim.x + threadIdx.x;
    if (i < n4) p[i] = make_float4(0.f, 0.f, 0.f, 0.f);
}

__global__ void scatter_add_kernel(const int* __restrict__ dst) {
    int i = blockIdx.x * blockDim.x + threadIdx.x;
    if (i >= N_EDGES * FD / 4) return;
    int e = i >> 7, c4 = i & 127;
    float4 v = *(const float4*)(g_msg + ((size_t)e << 9) + c4 * 4);
    float* base = g_agg + (size_t)dst[e] * FD + c4 * 4;
    atomicAdd(base + 0, v.x);
    atomicAdd(base + 1, v.y);
    atomicAdd(base + 2, v.z);
    atomicAdd(base + 3, v.w);
}

__global__ void edge_gather_kernel(const int* __restrict__ src, const int* __restrict__ dst) {
    int i = blockIdx.x * blockDim.x + threadIdx.x;
    if (i >= N_EDGES * FD / 4) return;
    int e = i >> 7, c4 = i & 127;
    const float4* s = (const float4*)(g_h + (size_t)src[e] * FD) + c4;
    const float4* d = (const float4*)(g_h + (size_t)dst[e] * FD) + c4;
    float4 a = *s, b = *d;
    a.x += b.x; a.y += b.y; a.z += b.z; a.w += b.w;
    *((float4*)(g_eh + ((size_t)e << 9)) + c4) = a;
}

// ---------------- tf32 tensor-core GEMM, 3-stage cp.async, warp tile 64x32 ----------------
// EPI: 0 plain | 1 +bias[n] | 2 relu(+extra[m*ld+n]) | 3 relu(+extra[gidx[m]*ld+n])
//      4 +extra[m*ld+n] | 5 gelu | 7 stats-only | 8 softmax-write

__device__ __forceinline__ void mma_tf32(float c[4], const uint32_t a[4], const uint32_t b[2]) {
    asm volatile(
        "mma.sync.aligned.m16n8k8.row.col.f32.tf32.tf32.f32 "
        "{%0,%1,%2,%3}, {%4,%5,%6,%7}, {%8,%9}, {%0,%1,%2,%3};"
        : "+f"(c[0]), "+f"(c[1]), "+f"(c[2]), "+f"(c[3])
        : "r"(a[0]), "r"(a[1]), "r"(a[2]), "r"(a[3]), "r"(b[0]), "r"(b[1]));
}

__device__ __forceinline__ void cp_async16(uint32_t dst, const void* src, bool pred) {
    int sz = pred ? 16 : 0;
    asm volatile("cp.async.cg.shared.global [%0], [%1], 16, %2;\n"
                 :: "r"(dst), "l"(src), "r"(sz));
}
__device__ __forceinline__ void cp_commit() {
    asm volatile("cp.async.commit_group;\n");
}
__device__ __forceinline__ void cp_wait0() {
    asm volatile("cp.async.wait_group 0;\n");
}
__device__ __forceinline__ void cp_wait1() {
    asm volatile("cp.async.wait_group 1;\n");
}

#define TBM 128
#define TBN 128
#define TBK 16
#define ASTR 20
#define BSTR 136
#define NSTAGE 3
#define SMEM_A_FLOATS (NSTAGE * TBM * ASTR)      // 7680
#define SMEM_B_FLOATS (NSTAGE * TBK * BSTR)      // 6528
#define GEMM_SMEM_BYTES ((SMEM_A_FLOATS + SMEM_B_FLOATS) * 4)   // 56832 B

template<int EPI>
__global__ void __launch_bounds__(256)
tmma_k(const float* __restrict__ A, const float* __restrict__ B, float* __restrict__ C,
       int M, int N, int K,
       const float* __restrict__ extra, const int* __restrict__ gidx, int ldex,
       float2* __restrict__ tstat) {
    extern __shared__ float smem[];
    float (*As)[TBM][ASTR] = (float(*)[TBM][ASTR])smem;
    float (*Bs)[TBK][BSTR] = (float(*)[TBK][BSTR])(smem + SMEM_A_FLOATS);
    float2 (*sstat)[4] = (float2(*)[4])smem;     // alias over As, post-mainloop only

    int tid  = threadIdx.x;
    int lane = tid & 31;
    int warp = tid >> 5;
    int wm = warp & 1;
    int wn = warp >> 1;
    int g   = lane >> 2;
    int tig = lane & 3;
    int m0 = blockIdx.y * TBM;
    int n0 = blockIdx.x * TBN;

    float acc[4][4][4] = {};

    int am[2], aq[2], bk[2], bn[2];
    #pragma unroll
    for (int i = 0; i < 2; i++) {
        int slot = tid + i * 256;
        am[i] = slot >> 2;
        aq[i] = (slot & 3) << 2;
        bk[i] = slot >> 5;
        bn[i] = (slot & 31) << 2;
    }

    auto issue_load = [&](int s, int k0) {
        #pragma unroll
        for (int i = 0; i < 2; i++) {
            uint32_t da = (uint32_t)__cvta_generic_to_shared(&As[s][am[i]][aq[i]]);
            cp_async16(da, A + (size_t)(m0 + am[i]) * K + k0 + aq[i], true);
            int gn = n0 + bn[i];
            uint32_t db = (uint32_t)__cvta_generic_to_shared(&Bs[s][bk[i]][bn[i]]);
            cp_async16(db, B + (size_t)(k0 + bk[i]) * N + gn, gn < N);
        }
    };

    int niter = K / TBK;    // >= 4 for all shapes used
    issue_load(0, 0);
    cp_commit();
    issue_load(1, TBK);
    cp_commit();

    for (int it = 0; it < niter; it++) {
        if (it == niter - 1) cp_wait0(); else cp_wait1();
        __syncthreads();
        if (it + 2 < niter) {
            issue_load((it + 2) % NSTAGE, (it + 2) * TBK);
            cp_commit();
        }
        int s = it % NSTAGE;
        #pragma unroll
        for (int ks = 0; ks < TBK; ks += 8) {
            uint32_t af[4][4], bf[4][2];
            #pragma unroll
            for (int mt = 0; mt < 4; mt++) {
                int rm = wm * 64 + mt * 16 + g;
                af[mt][0] = __float_as_uint(As[s][rm    ][ks + tig    ]);
                af[mt][1] = __float_as_uint(As[s][rm + 8][ks + tig    ]);
                af[mt][2] = __float_as_uint(As[s][rm    ][ks + tig + 4]);
                af[mt][3] = __float_as_uint(As[s][rm + 8][ks + tig + 4]);
            }
            #pragma unroll
            for (int nt = 0; nt < 4; nt++) {
                int cn = wn * 32 + nt * 8 + g;
                bf[nt][0] = __float_as_uint(Bs[s][ks + tig    ][cn]);
                bf[nt][1] = __float_as_uint(Bs[s][ks + tig + 4][cn]);
            }
            #pragma unroll
            for (int mt = 0; mt < 4; mt++)
                #pragma unroll
                for (int nt = 0; nt < 4; nt++)
                    mma_tf32(acc[mt][nt], af[mt], bf[nt]);
        }
    }

    if (EPI == 7) __syncthreads();   // protect sstat alias over As

    // ---------------- epilogue ----------------
    #pragma unroll
    for (int mt = 0; mt < 4; mt++) {
        #pragma unroll
        for (int half = 0; half < 2; half++) {
            int rib = wm * 64 + mt * 16 + half * 8 + g;
            int r = m0 + rib;
            int ebase = 0;
            if (EPI == 2 || EPI == 4) ebase = r * ldex;
            if (EPI == 3)             ebase = gidx[r] * ldex;
            float rmaxv = 0.0f, rinvv = 0.0f;
            if (EPI == 8) { rmaxv = g_rmax[r]; rinvv = g_rinv[r]; }

            float vals[8];
            #pragma unroll
            for (int nt = 0; nt < 4; nt++) {
                int n = n0 + wn * 32 + nt * 8 + 2 * tig;
                float c0 = acc[mt][nt][half * 2 + 0];
                float c1 = acc[mt][nt][half * 2 + 1];
                if (EPI == 1) { c0 += extra[n]; c1 += extra[n + 1]; }
                else if (EPI == 2 || EPI == 3) {
                    c0 = fmaxf(c0 + extra[ebase + n],     0.0f);
                    c1 = fmaxf(c1 + extra[ebase + n + 1], 0.0f);
                } else if (EPI == 4) {
                    c0 += extra[ebase + n]; c1 += extra[ebase + n + 1];
                } else if (EPI == 5) {
                    float x = c0;
                    c0 = 0.5f * x * (1.0f + tanhf(0.7978845608028654f * (x + 0.044715f * x * x * x)));
                    x = c1;
                    c1 = 0.5f * x * (1.0f + tanhf(0.7978845608028654f * (x + 0.044715f * x * x * x)));
                }
                vals[nt * 2 + 0] = c0;
                vals[nt * 2 + 1] = c1;
                if (EPI == 8) {
                    if (n < N) {
                        float p0 = __expf(c0 - rmaxv) * rinvv;
                        float p1 = __expf(c1 - rmaxv) * rinvv;
                        *(float2*)&C[(size_t)r * N + n] = make_float2(p0, p1);
                    }
                } else if (EPI != 7) {
                    if (n + 1 < N) {
                        *(float2*)&C[(size_t)r * N + n] = make_float2(c0, c1);
                    } else if (n < N) {
                        C[(size_t)r * N + n] = c0;
                    }
                }
            }

            if (EPI == 7) {
                float rmx = -1e30f;
                #pragma unroll
                for (int j = 0; j < 8; j++) {
                    int n = n0 + wn * 32 + (j >> 1) * 8 + 2 * tig + (j & 1);
                    float v = (n < N) ? vals[j] : -1e30f;
                    vals[j] = v;
                    rmx = fmaxf(rmx, v);
                }
                float rsm = 0.0f;
                #pragma unroll
                for (int j = 0; j < 8; j++) rsm += __expf(vals[j] - rmx);
                #pragma unroll
                for (int off = 1; off <= 2; off <<= 1) {
                    float om = __shfl_xor_sync(0xffffffffu, rmx, off);
                    float os = __shfl_xor_sync(0xffffffffu, rsm, off);
                    float nm = fmaxf(rmx, om);
                    rsm = rsm * __expf(rmx - nm) + os * __expf(om - nm);
                    rmx = nm;
                }
                if (tig == 0) sstat[rib][wn] = make_float2(rmx, rsm);
            }
        }
    }

    if (EPI == 7) {
        __syncthreads();
        if (tid < TBM) {
            float m = -1e30f, ssum = 0.0f;
            #pragma unroll
            for (int w = 0; w < 4; w++) {
                float2 p = sstat[tid][w];
                float nm = fmaxf(m, p.x);
                ssum = ssum * __expf(m - nm) + p.y * __expf(p.x - nm);
                m = nm;
            }
            tstat[(size_t)(m0 + tid) * gridDim.x + blockIdx.x] = make_float2(m, ssum);
        }
    }
}

// ---------------- softmax stat combine ----------------
__global__ void combine_stats_kernel(int ntile) {
    int row = blockIdx.x * blockDim.x + threadIdx.x;
    if (row >= ROWS) return;
    float m = -1e30f, s = 0.0f;
    for (int t = 0; t < ntile; t++) {
        float2 p = g_tstat[(size_t)row * ntile + t];
        float nm = fmaxf(m, p.x);
        s = s * __expf(m - nm) + p.y * __expf(p.x - nm);
        m = nm;
    }
    g_rmax[row] = m;
    g_rinv[row] = 1.0f / s;
}

// ---------------- attention ----------------
__global__ void __launch_bounds__(256) attention_kernel() {
    __shared__ float qs[8][DG], ks[8][DG], vs[8][DG];
    int b = blockIdx.x;
    int tid = threadIdx.x;
    for (int i = tid; i < 8 * DG; i += 256) {
        int s = i >> 8, c = i & 255;
        size_t off = (size_t)(b * 8 + s) * 768 + c;
        qs[s][c] = g_qkv[off];
        ks[s][c] = g_qkv[off + 256];
        vs[s][c] = g_qkv[off + 512];
    }
    __syncthreads();

    int h  = tid >> 6;
    int qx = (tid >> 3) & 7;
    int kx = tid & 7;
    float att = 0.0f;
    #pragma unroll
    for (int d = 0; d < HD; d++)
        att += qs[qx][h * HD + d] * ks[kx][h * HD + d];
    att *= 0.125f;

    float mx = att;
    mx = fmaxf(mx, __shfl_xor_sync(0xffffffffu, mx, 4));
    mx = fmaxf(mx, __shfl_xor_sync(0xffffffffu, mx, 2));
    mx = fmaxf(mx, __shfl_xor_sync(0xffffffffu, mx, 1));
    float ex = expf(att - mx);
    float sm = ex;
    sm += __shfl_xor_sync(0xffffffffu, sm, 4);
    sm += __shfl_xor_sync(0xffffffffu, sm, 2);
    sm += __shfl_xor_sync(0xffffffffu, sm, 1);
    float a = ex / sm;

    int lane = tid & 31;
    int base = lane & ~7;
    float a_all[8];
    #pragma unroll
    for (int kk = 0; kk < 8; kk++)
        a_all[kk] = __shfl_sync(0xffffffffu, a, base + kk);

    #pragma unroll
    for (int t2 = 0; t2 < 8; t2++) {
        int d = kx * 8 + t2;
        float o = 0.0f;
        #pragma unroll
        for (int kk = 0; kk < 8; kk++)
            o += a_all[kk] * vs[kk][h * HD + d];
        g_ao[(size_t)(b * 8 + qx) * DG + h * HD + d] = o;
    }
}

// ---------------- host launcher ----------------
template<int EPI>
static void launch_one(const float* A, const float* B, float* C, int M, int N, int K,
                       const float* extra, const int* gidx, int ldex, float2* tstat) {
    static bool attr_done = false;
    if (!attr_done) {
        cudaFuncSetAttribute(tmma_k<EPI>, cudaFuncAttributeMaxDynamicSharedMemorySize,
                             GEMM_SMEM_BYTES);
        attr_done = true;
    }
    dim3 grid((N + TBN - 1) / TBN, M / TBM), blk(256);
    tmma_k<EPI><<<grid, blk, GEMM_SMEM_BYTES>>>(A, B, C, M, N, K, extra, gidx, ldex, tstat);
}

static void launch_gemm(int epi, const float* A, const float* B, float* C,
                        int M, int N, int K,
                        const float* extra = nullptr, const int* gidx = nullptr, int ldex = 0,
                        float2* tstat = nullptr) {
    switch (epi) {
        case 0: launch_one<0>(A, B, C, M, N, K, extra, gidx, ldex, tstat); break;
        case 1: launch_one<1>(A, B, C, M, N, K, extra, gidx, ldex, tstat); break;
        case 2: launch_one<2>(A, B, C, M, N, K, extra, gidx, ldex, tstat); break;
        case 3: launch_one<3>(A, B, C, M, N, K, extra, gidx, ldex, tstat); break;
        case 4: launch_one<4>(A, B, C, M, N, K, extra, gidx, ldex, tstat); break;
        case 5: launch_one<5>(A, B, C, M, N, K, extra, gidx, ldex, tstat); break;
        case 7: launch_one<7>(A, B, C, M, N, K, extra, gidx, ldex, tstat); break;
        case 8: launch_one<8>(A, B, C, M, N, K, extra, gidx, ldex, tstat); break;
    }
}

template <typename T>
static T* sym_addr(const void* sym) {
    void* p = nullptr;
    cudaGetSymbolAddress(&p, sym);
    return (T*)p;
}

extern "C" void kernel_launch(void* const* d_in, const int* in_sizes, int n_in,
                              void* d_out, int out_size) {
    const int*   node_tokens = (const int*)d_in[0];
    const int*   edge_tokens = (const int*)d_in[1];
    const int*   edge_index  = (const int*)d_in[2];
    const void*  mask_rows   = d_in[3];
    const float* emb    = (const float*)d_in[4];
    const float* W_msg  = (const float*)d_in[5];
    const float* W_node = (const float*)d_in[6];
    const float* lc1_w  = (const float*)d_in[7];
    const float* lc1_b  = (const float*)d_in[8];
    const float* lc2_w  = (const float*)d_in[9];
    const float* lc2_b  = (const float*)d_in[10];
    const float* Wq  = (const float*)d_in[11];
    const float* Wk  = (const float*)d_in[12];
    const float* Wv  = (const float*)d_in[13];
    const float* Wo  = (const float*)d_in[14];
    const float* Wf1 = (const float*)d_in[15];
    const float* Wf2 = (const float*)d_in[16];

    float* out = (float*)d_out;
    bool concat = (out_size != ROWS * VOCAB);
    float* labels_out = concat ? out : nullptr;
    float* probs      = concat ? out + ROWS : out;

    const int* src = edge_index;
    const int* dst = edge_index + N_EDGES;

    float* px   = sym_addr<float>(g_x);
    float* pe   = sym_addr<float>(g_e);
    float* pmsg = sym_addr<float>(g_msg);
    float* pagg = sym_addr<float>(g_agg);
    float* ph   = sym_addr<float>(g_h);
    float* peh  = sym_addr<float>(g_eh);
    float* pzg  = sym_addr<float>(g_zg);
    float* pqkv = sym_addr<float>(g_qkv);
    float* pwqkv= sym_addr<float>(g_wqkv);
    float* pao  = sym_addr<float>(g_ao);
    float* px1  = sym_addr<float>(g_x1);
    float* pffn = sym_addr<float>(g_ffn);
    float* px2  = sym_addr<float>(g_x2);
    float* py   = sym_addr<float>(g_y);
    float* pembT= sym_addr<float>(g_embT);
    int*   pmt  = sym_addr<int>(g_mtok);
    float2* pst = sym_addr<float2>(g_tstat);

    // 1. mask dtype detect + labels/masked tokens
    detect_mask_kernel<<<1, 512>>>((const int*)mask_rows);
    mask_kernel<<<(N_EDGES * L_TOK + 255) / 256, 256>>>(edge_tokens, mask_rows, labels_out);

    // 2. embeddings + weight packing
    embed_kernel<<<(N_NODES * FD / 4 + 255) / 256, 256>>>(node_tokens, emb, (float4*)px, N_NODES * FD / 4);
    embed_kernel<<<(N_EDGES * FD / 4 + 255) / 256, 256>>>(pmt, emb, (float4*)pe, N_EDGES * FD / 4);
    transpose_emb_kernel<<<(D_GNN * VOCAB + 255) / 256, 256>>>(emb);
    pack_qkv_kernel<<<(DG * DG + 255) / 256, 256>>>(Wq, Wk, Wv);

    // 3. GNN
    launch_gemm(3, pe, W_msg, pmsg, N_EDGES, FD, FD, px, src, FD);
    zero_kernel<<<(N_NODES * FD / 4 + 255) / 256, 256>>>((float4*)pagg, N_NODES * FD / 4);
    scatter_add_kernel<<<(N_EDGES * FD / 4 + 255) / 256, 256>>>(dst);
    launch_gemm(2, px, W_node, ph, N_NODES, FD, FD, pagg, nullptr, FD);
    edge_gather_kernel<<<(N_EDGES * FD / 4 + 255) / 256, 256>>>(src, dst);

    // 4. lc1
    launch_gemm(1, peh, lc1_w, pzg, ROWS, DG, D_GNN, lc1_b);

    // 5. transformer
    launch_gemm(0, pzg, pwqkv, pqkv, ROWS, 3 * DG, DG);
    attention_kernel<<<N_EDGES, 256>>>();
    launch_gemm(4, pao, Wo, px1, ROWS, DG, DG, pzg, nullptr, DG);
    launch_gemm(5, px1, Wf1, pffn, ROWS, 4 * DG, DG);
    launch_gemm(4, pffn, Wf2, px2, ROWS, DG, 4 * DG, px1, nullptr, DG);

    // 6. lc2 + two-pass LM head
    launch_gemm(1, px2, lc2_w, py, ROWS, D_GNN, DG, lc2_b);
    launch_gemm(7, py, pembT, probs, ROWS, VOCAB, D_GNN, nullptr, nullptr, 0, pst);
    int ntile = (VOCAB + TBN - 1) / TBN;
    combine_stats_kernel<<<(ROWS + 255) / 256, 256>>>(ntile);
    launch_gemm(8, py, pembT, probs, ROWS, VOCAB, D_GNN, nullptr, nullptr, 0, pst);
}

// round 7
// speedup vs baseline: 1.7163x; 1.4211x over previous
#include <cuda_runtime.h>
#include <cuda_bf16.h>
#include <math.h>
#include <stdint.h>

// ---------------- problem constants ----------------
#define VOCAB   10000
#define D_GNN   64
#define L_TOK   8
#define DG      256
#define NH      4
#define HD      64
#define N_NODES 8192
#define N_EDGES 2048
#define FD      512
#define ROWS    16384
#define NTMAX   80

typedef __nv_bfloat16 bf16;

// ---------------- scratch (static device memory) ----------------
__device__ bf16  g_x   [N_NODES * FD];
__device__ bf16  g_e   [N_EDGES * FD];
__device__ bf16  g_msg [N_EDGES * FD];
__device__ float g_agg [N_NODES * FD];          // fp32 accumulation
__device__ bf16  g_h   [N_NODES * FD];
__device__ bf16  g_eh  [N_EDGES * FD];
__device__ bf16  g_zg  [ROWS * DG];
__device__ bf16  g_qkv [ROWS * 3 * DG];
__device__ bf16  g_ao  [ROWS * DG];
__device__ bf16  g_x1  [ROWS * DG];
__device__ bf16  g_ffn [ROWS * 4 * DG];
__device__ bf16  g_x2  [ROWS * DG];
__device__ bf16  g_y   [ROWS * D_GNN];
// bf16 weight copies
__device__ bf16  g_wmsg [FD * FD];
__device__ bf16  g_wnode[FD * FD];
__device__ bf16  g_lc1w [D_GNN * DG];
__device__ bf16  g_lc2w [DG * D_GNN];
__device__ bf16  g_wo   [DG * DG];
__device__ bf16  g_wf1  [DG * 4 * DG];
__device__ bf16  g_wf2  [4 * DG * DG];
__device__ bf16  g_wqkv [DG * 3 * DG];
__device__ bf16  g_embf [VOCAB * D_GNN];        // bf16 emb table
__device__ bf16  g_embT [D_GNN * VOCAB];        // bf16 emb transposed
__device__ int   g_mtok[N_EDGES * L_TOK];
__device__ float2 g_tstat[ROWS * NTMAX];
__device__ float g_rmax[ROWS];
__device__ float g_rinv[ROWS];
__device__ int   g_mask_mode;

// ---------------- mask dtype detection ----------------
__global__ void detect_mask_kernel(const int* __restrict__ mr) {
    __shared__ int notint, notflt;
    if (threadIdx.x == 0) { notint = 0; notflt = 0; }
    __syncthreads();
    int w = mr[threadIdx.x];
    if (w != 0 && w != 1)          atomicExch(&notint, 1);
    if (w != 0 && w != 0x3F800000) atomicExch(&notflt, 1);
    __syncthreads();
    if (threadIdx.x == 0)
        g_mask_mode = notint ? (notflt ? 2 : 1) : 0;
}

__global__ void mask_kernel(const int* __restrict__ etok, const void* __restrict__ maskraw,
                            float* labels_out) {
    int i = blockIdx.x * blockDim.x + threadIdx.x;
    if (i >= N_EDGES * L_TOK) return;
    int e = i >> 3;
    int t = etok[i];
    bool mr;
    int mode = g_mask_mode;
    if (mode == 0)      mr = ((const int*)maskraw)[e] != 0;
    else if (mode == 1) mr = ((const float*)maskraw)[e] != 0.0f;
    else                mr = ((const unsigned char*)maskraw)[e] != 0;
    bool msk = mr && (t >= 4);
    g_mtok[i] = msk ? 4 : t;
    if (labels_out) labels_out[i] = msk ? (float)t : -100.0f;
}

// ---------------- conversions ----------------
__global__ void convert_emb_kernel(const float* __restrict__ emb) {
    int i = blockIdx.x * blockDim.x + threadIdx.x;
    if (i < VOCAB * D_GNN) g_embf[i] = __float2bfloat16_rn(emb[i]);
}

__global__ void transpose_emb_kernel(const float* __restrict__ emb) {
    int i = blockIdx.x * blockDim.x + threadIdx.x;
    if (i >= D_GNN * VOCAB) return;
    int k = i / VOCAB, v = i - k * VOCAB;
    g_embT[i] = __float2bfloat16_rn(emb[v * 64 + k]);
}

#define SZ_WMSG  (FD*FD)
#define SZ_WNODE (FD*FD)
#define SZ_LC1   (D_GNN*DG)
#define SZ_LC2   (DG*D_GNN)
#define SZ_WO    (DG*DG)
#define SZ_WF1   (DG*4*DG)
#define SZ_WF2   (4*DG*DG)
#define CW_TOTAL (SZ_WMSG+SZ_WNODE+SZ_LC1+SZ_LC2+SZ_WO+SZ_WF1+SZ_WF2)

__global__ void convert_weights_kernel(const float* Wmsg, const float* Wnode,
                                       const float* lc1w, const float* lc2w,
                                       const float* Wo, const float* Wf1, const float* Wf2) {
    int i = blockIdx.x * blockDim.x + threadIdx.x;
    if (i >= CW_TOTAL) return;
    int j = i;
    if (j < SZ_WMSG)  { g_wmsg[j]  = __float2bfloat16_rn(Wmsg[j]);  return; } j -= SZ_WMSG;
    if (j < SZ_WNODE) { g_wnode[j] = __float2bfloat16_rn(Wnode[j]); return; } j -= SZ_WNODE;
    if (j < SZ_LC1)   { g_lc1w[j]  = __float2bfloat16_rn(lc1w[j]);  return; } j -= SZ_LC1;
    if (j < SZ_LC2)   { g_lc2w[j]  = __float2bfloat16_rn(lc2w[j]);  return; } j -= SZ_LC2;
    if (j < SZ_WO)    { g_wo[j]    = __float2bfloat16_rn(Wo[j]);    return; } j -= SZ_WO;
    if (j < SZ_WF1)   { g_wf1[j]   = __float2bfloat16_rn(Wf1[j]);   return; } j -= SZ_WF1;
    g_wf2[j] = __float2bfloat16_rn(Wf2[j]);
}

__global__ void pack_qkv_kernel(const float* __restrict__ Wq, const float* __restrict__ Wk,
                                const float* __restrict__ Wv) {
    int i = blockIdx.x * blockDim.x + threadIdx.x;
    if (i >= DG * DG) return;
    int k = i >> 8, n = i & 255;
    g_wqkv[k * 768 + n]       = __float2bfloat16_rn(Wq[i]);
    g_wqkv[k * 768 + 256 + n] = __float2bfloat16_rn(Wk[i]);
    g_wqkv[k * 768 + 512 + n] = __float2bfloat16_rn(Wv[i]);
}

// embedding gather: 16B (8 bf16) per thread; table rows are 128B = 8 uint4
__global__ void embed_kernel(const int* __restrict__ tok, uint4* __restrict__ out, int total16) {
    int i = blockIdx.x * blockDim.x + threadIdx.x;
    if (i >= total16) return;
    int ti = i >> 3;
    int d  = i & 7;
    out[i] = ((const uint4*)g_embf)[tok[ti] * 8 + d];
}

__global__ void zero_kernel(float4* __restrict__ p, int n4) {
    int i = blockIdx.x * blockDim.x + threadIdx.x;
    if (i < n4) p[i] = make_float4(0.f, 0.f, 0.f, 0.f);
}

__device__ __forceinline__ void unpack8(uint4 raw, float* v) {
    const __nv_bfloat162* h = (const __nv_bfloat162*)&raw;
    #pragma unroll
    for (int j = 0; j < 4; j++) {
        v[2*j]   = __bfloat162float(h[j].x);
        v[2*j+1] = __bfloat162float(h[j].y);
    }
}

__global__ void scatter_add_kernel(const int* __restrict__ dst) {
    int i = blockIdx.x * blockDim.x + threadIdx.x;     // 8-elem chunk
    if (i >= N_EDGES * FD / 8) return;
    int e = i >> 6, c8 = (i & 63) * 8;
    uint4 raw = *(const uint4*)(g_msg + ((size_t)e << 9) + c8);
    float v[8]; unpack8(raw, v);
    float* base = g_agg + (size_t)dst[e] * FD + c8;
    #pragma unroll
    for (int j = 0; j < 8; j++) atomicAdd(base + j, v[j]);
}

__global__ void edge_gather_kernel(const int* __restrict__ src, const int* __restrict__ dst) {
    int i = blockIdx.x * blockDim.x + threadIdx.x;     // 8-elem chunk
    if (i >= N_EDGES * FD / 8) return;
    int e = i >> 6, c8 = (i & 63) * 8;
    uint4 ra = *(const uint4*)(g_h + (size_t)src[e] * FD + c8);
    uint4 rb = *(const uint4*)(g_h + (size_t)dst[e] * FD + c8);
    float a[8], b[8]; unpack8(ra, a); unpack8(rb, b);
    __nv_bfloat162 o[4];
    #pragma unroll
    for (int j = 0; j < 4; j++) {
        o[j].x = __float2bfloat16_rn(a[2*j]   + b[2*j]);
        o[j].y = __float2bfloat16_rn(a[2*j+1] + b[2*j+1]);
    }
    *(uint4*)(g_eh + ((size_t)e << 9) + c8) = *(uint4*)o;
}

// ---------------- bf16 tensor-core GEMM, 3-stage cp.async, ldmatrix ----------------
// EPI: 0 plain | 1 +biasf[n] | 2 relu(+extraf[m*ld+n]) | 3 relu(+extrab[gidx[m]*ld+n])
//      4 +extrab[m*ld+n] | 5 gelu | 7 stats-only | 8 softmax-write (fp32 C)

__device__ __forceinline__ void mma_bf16(float c[4], const uint32_t a[4], const uint32_t b[2]) {
    asm volatile(
        "mma.sync.aligned.m16n8k16.row.col.f32.bf16.bf16.f32 "
        "{%0,%1,%2,%3}, {%4,%5,%6,%7}, {%8,%9}, {%0,%1,%2,%3};"
        : "+f"(c[0]), "+f"(c[1]), "+f"(c[2]), "+f"(c[3])
        : "r"(a[0]), "r"(a[1]), "r"(a[2]), "r"(a[3]), "r"(b[0]), "r"(b[1]));
}

__device__ __forceinline__ void ldsm_x4(uint32_t& r0, uint32_t& r1, uint32_t& r2, uint32_t& r3,
                                        uint32_t addr) {
    asm volatile("ldmatrix.sync.aligned.m8n8.x4.shared.b16 {%0,%1,%2,%3}, [%4];"
                 : "=r"(r0), "=r"(r1), "=r"(r2), "=r"(r3) : "r"(addr));
}
__device__ __forceinline__ void ldsm_x4_t(uint32_t& r0, uint32_t& r1, uint32_t& r2, uint32_t& r3,
                                          uint32_t addr) {
    asm volatile("ldmatrix.sync.aligned.m8n8.x4.trans.shared.b16 {%0,%1,%2,%3}, [%4];"
                 : "=r"(r0), "=r"(r1), "=r"(r2), "=r"(r3) : "r"(addr));
}

__device__ __forceinline__ void cp_async16(uint32_t dst, const void* src, bool pred) {
    int sz = pred ? 16 : 0;
    asm volatile("cp.async.cg.shared.global [%0], [%1], 16, %2;\n"
                 :: "r"(dst), "l"(src), "r"(sz));
}
__device__ __forceinline__ void cp_commit() { asm volatile("cp.async.commit_group;\n"); }
__device__ __forceinline__ void cp_wait0()  { asm volatile("cp.async.wait_group 0;\n"); }
__device__ __forceinline__ void cp_wait1()  { asm volatile("cp.async.wait_group 1;\n"); }

#define TBM 128
#define TBN 128
#define TBK 32
#define ASTRH 40      // A row stride in bf16 (80B): ldmatrix groups 20r mod 32, disjoint
#define BSTRH 136     // B row stride in bf16 (272B): groups 4r, disjoint
#define NSTAGE 3
#define A_STAGE_H (TBM * ASTRH)      // 5120 halves
#define B_STAGE_H (TBK * BSTRH)      // 4352 halves
#define GEMM_SMEM_BYTES (NSTAGE * (A_STAGE_H + B_STAGE_H) * 2)   // 56832 B

template<int EPI>
__global__ void __launch_bounds__(256)
tmma_k(const bf16* __restrict__ A, const bf16* __restrict__ B, void* __restrict__ Cv,
       int M, int N, int K,
       const float* __restrict__ extraf, const bf16* __restrict__ extrab,
       const int* __restrict__ gidx, int ldex, float2* __restrict__ tstat) {
    extern __shared__ bf16 smem[];
    bf16* Asm = smem;
    bf16* Bsm = smem + NSTAGE * A_STAGE_H;
    float2 (*sstat)[4] = (float2(*)[4])smem;     // alias, post-mainloop only

    uint32_t aU = (uint32_t)__cvta_generic_to_shared(Asm);
    uint32_t bU = (uint32_t)__cvta_generic_to_shared(Bsm);

    int tid  = threadIdx.x;
    int lane = tid & 31;
    int warp = tid >> 5;
    int wm = warp & 1;
    int wn = warp >> 1;
    int g   = lane >> 2;
    int tig = lane & 3;
    int m0 = blockIdx.y * TBM;
    int n0 = blockIdx.x * TBN;

    float acc[4][4][4] = {};

    auto issue_load = [&](int s, int k0) {
        #pragma unroll
        for (int i = 0; i < 2; i++) {
            int id = tid + i * 256;
            int ar = id >> 2, ak = (id & 3) << 3;
            uint32_t da = aU + (s * A_STAGE_H + ar * ASTRH + ak) * 2;
            cp_async16(da, A + (size_t)(m0 + ar) * K + k0 + ak, true);
            int br = id >> 4, bn = (id & 15) << 3;
            int gn = n0 + bn;
            uint32_t db = bU + (s * B_STAGE_H + br * BSTRH + bn) * 2;
            cp_async16(db, B + (size_t)(k0 + br) * N + gn, gn + 8 <= N);
        }
    };

    int niter = K / TBK;     // >= 2 for all shapes used
    issue_load(0, 0);
    cp_commit();
    issue_load(1, TBK);
    cp_commit();

    for (int it = 0; it < niter; it++) {
        if (it == niter - 1) cp_wait0(); else cp_wait1();
        __syncthreads();
        if (it + 2 < niter) {
            issue_load((it + 2) % NSTAGE, (it + 2) * TBK);
            cp_commit();
        }
        int s = it % NSTAGE;
        uint32_t aB = aU + s * A_STAGE_H * 2;
        uint32_t bB = bU + s * B_STAGE_H * 2;
        #pragma unroll
        for (int ks = 0; ks < TBK; ks += 16) {
            uint32_t af[4][4], bf[4][2];
            #pragma unroll
            for (int mt = 0; mt < 4; mt++) {
                int row = wm * 64 + mt * 16 + (lane & 15);
                uint32_t ad = aB + (row * ASTRH + ks + ((lane >> 4) << 3)) * 2;
                ldsm_x4(af[mt][0], af[mt][1], af[mt][2], af[mt][3], ad);
            }
            #pragma unroll
            for (int bp = 0; bp < 2; bp++) {
                int krow = ks + (lane & 15);
                int ncol = wn * 32 + bp * 16 + ((lane >> 4) << 3);
                uint32_t bd = bB + (krow * BSTRH + ncol) * 2;
                ldsm_x4_t(bf[2*bp][0], bf[2*bp][1], bf[2*bp+1][0], bf[2*bp+1][1], bd);
            }
            #pragma unroll
            for (int mt = 0; mt < 4; mt++)
                #pragma unroll
                for (int nt = 0; nt < 4; nt++)
                    mma_bf16(acc[mt][nt], af[mt], bf[nt]);
        }
    }

    if (EPI == 7) __syncthreads();    // protect sstat alias

    bf16*  Cb = (bf16*)Cv;
    float* Cf = (float*)Cv;

    // ---------------- epilogue ----------------
    #pragma unroll
    for (int mt = 0; mt < 4; mt++) {
        #pragma unroll
        for (int half = 0; half < 2; half++) {
            int rib = wm * 64 + mt * 16 + half * 8 + g;
            int r = m0 + rib;
            int ebase = 0;
            if (EPI == 2 || EPI == 4) ebase = r * ldex;
            if (EPI == 3)             ebase = gidx[r] * ldex;
            float rmaxv = 0.0f, rinvv = 0.0f;
            if (EPI == 8) { rmaxv = g_rmax[r]; rinvv = g_rinv[r]; }

            float vals[8];
            #pragma unroll
            for (int nt = 0; nt < 4; nt++) {
                int n = n0 + wn * 32 + nt * 8 + 2 * tig;
                float c0 = acc[mt][nt][half * 2 + 0];
                float c1 = acc[mt][nt][half * 2 + 1];
                if (EPI == 1) { c0 += extraf[n]; c1 += extraf[n + 1]; }
                else if (EPI == 2) {
                    c0 = fmaxf(c0 + extraf[ebase + n],     0.0f);
                    c1 = fmaxf(c1 + extraf[ebase + n + 1], 0.0f);
                } else if (EPI == 3) {
                    c0 = fmaxf(c0 + __bfloat162float(extrab[ebase + n]),     0.0f);
                    c1 = fmaxf(c1 + __bfloat162float(extrab[ebase + n + 1]), 0.0f);
                } else if (EPI == 4) {
                    c0 += __bfloat162float(extrab[ebase + n]);
                    c1 += __bfloat162float(extrab[ebase + n + 1]);
                } else if (EPI == 5) {
                    float x = c0;
                    c0 = 0.5f * x * (1.0f + tanhf(0.7978845608028654f * (x + 0.044715f * x * x * x)));
                    x = c1;
                    c1 = 0.5f * x * (1.0f + tanhf(0.7978845608028654f * (x + 0.044715f * x * x * x)));
                }
                vals[nt * 2 + 0] = c0;
                vals[nt * 2 + 1] = c1;
                if (EPI == 8) {
                    if (n < N) {
                        float p0 = __expf(c0 - rmaxv) * rinvv;
                        float p1 = __expf(c1 - rmaxv) * rinvv;
                        *(float2*)&Cf[(size_t)r * N + n] = make_float2(p0, p1);
                    }
                } else if (EPI != 7) {
                    if (n + 1 < N) {
                        __nv_bfloat162 p;
                        p.x = __float2bfloat16_rn(c0);
                        p.y = __float2bfloat16_rn(c1);
                        *(__nv_bfloat162*)&Cb[(size_t)r * N + n] = p;
                    }
                }
            }

            if (EPI == 7) {
                float rmx = -1e30f;
                #pragma unroll
                for (int j = 0; j < 8; j++) {
                    int n = n0 + wn * 32 + (j >> 1) * 8 + 2 * tig + (j & 1);
                    float v = (n < N) ? vals[j] : -1e30f;
                    vals[j] = v;
                    rmx = fmaxf(rmx, v);
                }
                float rsm = 0.0f;
                #pragma unroll
                for (int j = 0; j < 8; j++) rsm += __expf(vals[j] - rmx);
                #pragma unroll
                for (int off = 1; off <= 2; off <<= 1) {
                    float om = __shfl_xor_sync(0xffffffffu, rmx, off);
                    float os = __shfl_xor_sync(0xffffffffu, rsm, off);
                    float nm = fmaxf(rmx, om);
                    rsm = rsm * __expf(rmx - nm) + os * __expf(om - nm);
                    rmx = nm;
                }
                if (tig == 0) sstat[rib][wn] = make_float2(rmx, rsm);
            }
        }
    }

    if (EPI == 7) {
        __syncthreads();
        if (tid < TBM) {
            float m = -1e30f, ssum = 0.0f;
            #pragma unroll
            for (int w = 0; w < 4; w++) {
                float2 p = sstat[tid][w];
                float nm = fmaxf(m, p.x);
                ssum = ssum * __expf(m - nm) + p.y * __expf(p.x - nm);
                m = nm;
            }
            tstat[(size_t)(m0 + tid) * gridDim.x + blockIdx.x] = make_float2(m, ssum);
        }
    }
}

// ---------------- softmax stat combine ----------------
__global__ void combine_stats_kernel(int ntile) {
    int row = blockIdx.x * blockDim.x + threadIdx.x;
    if (row >= ROWS) return;
    float m = -1e30f, s = 0.0f;
    for (int t = 0; t < ntile; t++) {
        float2 p = g_tstat[(size_t)row * ntile + t];
        float nm = fmaxf(m, p.x);
        s = s * __expf(m - nm) + p.y * __expf(p.x - nm);
        m = nm;
    }
    g_rmax[row] = m;
    g_rinv[row] = 1.0f / s;
}

// ---------------- attention ----------------
__global__ void __launch_bounds__(256) attention_kernel() {
    __shared__ float qs[8][DG], ks[8][DG], vs[8][DG];
    int b = blockIdx.x;
    int tid = threadIdx.x;
    for (int i = tid; i < 8 * DG; i += 256) {
        int s = i >> 8, c = i & 255;
        size_t off = (size_t)(b * 8 + s) * 768 + c;
        qs[s][c] = __bfloat162float(g_qkv[off]);
        ks[s][c] = __bfloat162float(g_qkv[off + 256]);
        vs[s][c] = __bfloat162float(g_qkv[off + 512]);
    }
    __syncthreads();

    int h  = tid >> 6;
    int qx = (tid >> 3) & 7;
    int kx = tid & 7;
    float att = 0.0f;
    #pragma unroll
    for (int d = 0; d < HD; d++)
        att += qs[qx][h * HD + d] * ks[kx][h * HD + d];
    att *= 0.125f;

    float mx = att;
    mx = fmaxf(mx, __shfl_xor_sync(0xffffffffu, mx, 4));
    mx = fmaxf(mx, __shfl_xor_sync(0xffffffffu, mx, 2));
    mx = fmaxf(mx, __shfl_xor_sync(0xffffffffu, mx, 1));
    float ex = expf(att - mx);
    float sm = ex;
    sm += __shfl_xor_sync(0xffffffffu, sm, 4);
    sm += __shfl_xor_sync(0xffffffffu, sm, 2);
    sm += __shfl_xor_sync(0xffffffffu, sm, 1);
    float a = ex / sm;

    int lane = tid & 31;
    int base = lane & ~7;
    float a_all[8];
    #pragma unroll
    for (int kk = 0; kk < 8; kk++)
        a_all[kk] = __shfl_sync(0xffffffffu, a, base + kk);

    #pragma unroll
    for (int t2 = 0; t2 < 8; t2++) {
        int d = kx * 8 + t2;
        float o = 0.0f;
        #pragma unroll
        for (int kk = 0; kk < 8; kk++)
            o += a_all[kk] * vs[kk][h * HD + d];
        g_ao[(size_t)(b * 8 + qx) * DG + h * HD + d] = __float2bfloat16_rn(o);
    }
}

// ---------------- host launcher ----------------
template<int EPI>
static void launch_one(const bf16* A, const bf16* B, void* C, int M, int N, int K,
                       const float* extraf, const bf16* extrab,
                       const int* gidx, int ldex, float2* tstat) {
    static bool attr_done = false;
    if (!attr_done) {
        cudaFuncSetAttribute(tmma_k<EPI>, cudaFuncAttributeMaxDynamicSharedMemorySize,
                             GEMM_SMEM_BYTES);
        attr_done = true;
    }
    dim3 grid((N + TBN - 1) / TBN, M / TBM), blk(256);
    tmma_k<EPI><<<grid, blk, GEMM_SMEM_BYTES>>>(A, B, C, M, N, K, extraf, extrab,
                                                gidx, ldex, tstat);
}

static void launch_gemm(int epi, const bf16* A, const bf16* B, void* C,
                        int M, int N, int K,
                        const float* extraf = nullptr, const bf16* extrab = nullptr,
                        const int* gidx = nullptr, int ldex = 0, float2* tstat = nullptr) {
    switch (epi) {
        case 0: launch_one<0>(A, B, C, M, N, K, extraf, extrab, gidx, ldex, tstat); break;
        case 1: launch_one<1>(A, B, C, M, N, K, extraf, extrab, gidx, ldex, tstat); break;
        case 2: launch_one<2>(A, B, C, M, N, K, extraf, extrab, gidx, ldex, tstat); break;
        case 3: launch_one<3>(A, B, C, M, N, K, extraf, extrab, gidx, ldex, tstat); break;
        case 4: launch_one<4>(A, B, C, M, N, K, extraf, extrab, gidx, ldex, tstat); break;
        case 5: launch_one<5>(A, B, C, M, N, K, extraf, extrab, gidx, ldex, tstat); break;
        case 7: launch_one<7>(A, B, C, M, N, K, extraf, extrab, gidx, ldex, tstat); break;
        case 8: launch_one<8>(A, B, C, M, N, K, extraf, extrab, gidx, ldex, tstat); break;
    }
}

template <typename T>
static T* sym_addr(const void* sym) {
    void* p = nullptr;
    cudaGetSymbolAddress(&p, sym);
    return (T*)p;
}

extern "C" void kernel_launch(void* const* d_in, const int* in_sizes, int n_in,
                              void* d_out, int out_size) {
    const int*   node_tokens = (const int*)d_in[0];
    const int*   edge_tokens = (const int*)d_in[1];
    const int*   edge_index  = (const int*)d_in[2];
    const void*  mask_rows   = d_in[3];
    const float* emb    = (const float*)d_in[4];
    const float* W_msg  = (const float*)d_in[5];
    const float* W_node = (const float*)d_in[6];
    const float* lc1_w  = (const float*)d_in[7];
    const float* lc1_b  = (const float*)d_in[8];
    const float* lc2_w  = (const float*)d_in[9];
    const float* lc2_b  = (const float*)d_in[10];
    const float* Wq  = (const float*)d_in[11];
    const float* Wk  = (const float*)d_in[12];
    const float* Wv  = (const float*)d_in[13];
    const float* Wo  = (const float*)d_in[14];
    const float* Wf1 = (const float*)d_in[15];
    const float* Wf2 = (const float*)d_in[16];

    float* out = (float*)d_out;
    bool concat = (out_size != ROWS * VOCAB);
    float* labels_out = concat ? out : nullptr;
    float* probs      = concat ? out + ROWS : out;

    const int* src = edge_index;
    const int* dst = edge_index + N_EDGES;

    bf16* px   = sym_addr<bf16>(g_x);
    bf16* pe   = sym_addr<bf16>(g_e);
    bf16* pmsg = sym_addr<bf16>(g_msg);
    float* pagg= sym_addr<float>(g_agg);
    bf16* ph   = sym_addr<bf16>(g_h);
    bf16* peh  = sym_addr<bf16>(g_eh);
    bf16* pzg  = sym_addr<bf16>(g_zg);
    bf16* pqkv = sym_addr<bf16>(g_qkv);
    bf16* pao  = sym_addr<bf16>(g_ao);
    bf16* px1  = sym_addr<bf16>(g_x1);
    bf16* pffn = sym_addr<bf16>(g_ffn);
    bf16* px2  = sym_addr<bf16>(g_x2);
    bf16* py   = sym_addr<bf16>(g_y);
    bf16* pembT= sym_addr<bf16>(g_embT);
    bf16* pwmsg = sym_addr<bf16>(g_wmsg);
    bf16* pwnode= sym_addr<bf16>(g_wnode);
    bf16* plc1w = sym_addr<bf16>(g_lc1w);
    bf16* plc2w = sym_addr<bf16>(g_lc2w);
    bf16* pwo   = sym_addr<bf16>(g_wo);
    bf16* pwf1  = sym_addr<bf16>(g_wf1);
    bf16* pwf2  = sym_addr<bf16>(g_wf2);
    bf16* pwqkv = sym_addr<bf16>(g_wqkv);
    int*  pmt   = sym_addr<int>(g_mtok);
    float2* pst = sym_addr<float2>(g_tstat);

    // 1. mask dtype detect + labels/masked tokens
    detect_mask_kernel<<<1, 512>>>((const int*)mask_rows);
    mask_kernel<<<(N_EDGES * L_TOK + 255) / 256, 256>>>(edge_tokens, mask_rows, labels_out);

    // 2. conversions + embeddings
    convert_emb_kernel<<<(VOCAB * D_GNN + 255) / 256, 256>>>(emb);
    transpose_emb_kernel<<<(D_GNN * VOCAB + 255) / 256, 256>>>(emb);
    convert_weights_kernel<<<(CW_TOTAL + 255) / 256, 256>>>(W_msg, W_node, lc1_w, lc2_w,
                                                            Wo, Wf1, Wf2);
    pack_qkv_kernel<<<(DG * DG + 255) / 256, 256>>>(Wq, Wk, Wv);
    embed_kernel<<<(N_NODES * FD / 8 + 255) / 256, 256>>>(node_tokens, (uint4*)px, N_NODES * FD / 8);
    embed_kernel<<<(N_EDGES * FD / 8 + 255) / 256, 256>>>(pmt, (uint4*)pe, N_EDGES * FD / 8);

    // 3. GNN
    launch_gemm(3, pe, pwmsg, pmsg, N_EDGES, FD, FD, nullptr, px, src, FD);
    zero_kernel<<<(N_NODES * FD / 4 + 255) / 256, 256>>>((float4*)pagg, N_NODES * FD / 4);
    scatter_add_kernel<<<(N_EDGES * FD / 8 + 255) / 256, 256>>>(dst);
    launch_gemm(2, px, pwnode, ph, N_NODES, FD, FD, pagg, nullptr, nullptr, FD);
    edge_gather_kernel<<<(N_EDGES * FD / 8 + 255) / 256, 256>>>(src, dst);

    // 4. lc1
    launch_gemm(1, peh, plc1w, pzg, ROWS, DG, D_GNN, lc1_b);

    // 5. transformer
    launch_gemm(0, pzg, pwqkv, pqkv, ROWS, 3 * DG, DG);
    attention_kernel<<<N_EDGES, 256>>>();
    launch_gemm(4, pao, pwo, px1, ROWS, DG, DG, nullptr, pzg, nullptr, DG);
    launch_gemm(5, px1, pwf1, pffn, ROWS, 4 * DG, DG);
    launch_gemm(4, pffn, pwf2, px2, ROWS, DG, 4 * DG, nullptr, px1, nullptr, DG);

    // 6. lc2 + two-pass LM head
    launch_gemm(1, px2, plc2w, py, ROWS, D_GNN, DG, lc2_b);
    launch_gemm(7, py, pembT, probs, ROWS, VOCAB, D_GNN, nullptr, nullptr, nullptr, 0, pst);
    int ntile = (VOCAB + TBN - 1) / TBN;
    combine_stats_kernel<<<(ROWS + 255) / 256, 256>>>(ntile);
    launch_gemm(8, py, pembT, probs, ROWS, VOCAB, D_GNN, nullptr, nullptr, nullptr, 0, pst);
}

// round 9
// speedup vs baseline: 1.9028x; 1.1086x over previous
#include <cuda_runtime.h>
#include <cuda_bf16.h>
#include <math.h>
#include <stdint.h>

// ---------------- problem constants ----------------
#define VOCAB   10000
#define D_GNN   64
#define L_TOK   8
#define DG      256
#define NH      4
#define HD      64
#define N_NODES 8192
#define N_EDGES 2048
#define FD      512
#define ROWS    16384

typedef __nv_bfloat16 bf16;

// ---------------- scratch (static device memory) ----------------
__device__ bf16  g_x   [N_NODES * FD];
__device__ bf16  g_e   [N_EDGES * FD];
__device__ bf16  g_msg [N_EDGES * FD];
__device__ float g_agg [N_NODES * FD];
__device__ bf16  g_h   [N_NODES * FD];
__device__ bf16  g_eh  [N_EDGES * FD];
__device__ bf16  g_zg  [ROWS * DG];
__device__ bf16  g_qkv [ROWS * 3 * DG];
__device__ bf16  g_ao  [ROWS * DG];
__device__ bf16  g_x1  [ROWS * DG];
__device__ bf16  g_ffn [ROWS * 4 * DG];
__device__ bf16  g_x2  [ROWS * DG];
__device__ bf16  g_y   [ROWS * D_GNN];
__device__ bf16  g_wmsg [FD * FD];
__device__ bf16  g_wnode[FD * FD];
__device__ bf16  g_lc1w [D_GNN * DG];
__device__ bf16  g_lc2w [DG * D_GNN];
__device__ bf16  g_wo   [DG * DG];
__device__ bf16  g_wf1  [DG * 4 * DG];
__device__ bf16  g_wf2  [4 * DG * DG];
__device__ bf16  g_wqkv [DG * 3 * DG];
__device__ bf16  g_embf [VOCAB * D_GNN];     // bf16 emb table [V,64]; LM-head B read n-major
__device__ int   g_mtok[N_EDGES * L_TOK];
__device__ int   g_mask_mode;

// ---------------- mask dtype detection ----------------
__global__ void detect_mask_kernel(const int* __restrict__ mr) {
    __shared__ int notint, notflt;
    if (threadIdx.x == 0) { notint = 0; notflt = 0; }
    __syncthreads();
    int w = mr[threadIdx.x];
    if (w != 0 && w != 1)          atomicExch(&notint, 1);
    if (w != 0 && w != 0x3F800000) atomicExch(&notflt, 1);
    __syncthreads();
    if (threadIdx.x == 0)
        g_mask_mode = notint ? (notflt ? 2 : 1) : 0;
}

__global__ void mask_kernel(const int* __restrict__ etok, const void* __restrict__ maskraw,
                            float* labels_out) {
    int i = blockIdx.x * blockDim.x + threadIdx.x;
    if (i >= N_EDGES * L_TOK) return;
    int e = i >> 3;
    int t = etok[i];
    bool mr;
    int mode = g_mask_mode;
    if (mode == 0)      mr = ((const int*)maskraw)[e] != 0;
    else if (mode == 1) mr = ((const float*)maskraw)[e] != 0.0f;
    else                mr = ((const unsigned char*)maskraw)[e] != 0;
    bool msk = mr && (t >= 4);
    g_mtok[i] = msk ? 4 : t;
    if (labels_out) labels_out[i] = msk ? (float)t : -100.0f;
}

// ---------------- conversions ----------------
__global__ void convert_emb_kernel(const float* __restrict__ emb) {
    int i = blockIdx.x * blockDim.x + threadIdx.x;
    if (i < VOCAB * D_GNN) g_embf[i] = __float2bfloat16_rn(emb[i]);
}

#define SZ_WMSG  (FD*FD)
#define SZ_WNODE (FD*FD)
#define SZ_LC1   (D_GNN*DG)
#define SZ_LC2   (DG*D_GNN)
#define SZ_WO    (DG*DG)
#define SZ_WF1   (DG*4*DG)
#define SZ_WF2   (4*DG*DG)
#define CW_TOTAL (SZ_WMSG+SZ_WNODE+SZ_LC1+SZ_LC2+SZ_WO+SZ_WF1+SZ_WF2)

__global__ void convert_weights_kernel(const float* Wmsg, const float* Wnode,
                                       const float* lc1w, const float* lc2w,
                                       const float* Wo, const float* Wf1, const float* Wf2) {
    int i = blockIdx.x * blockDim.x + threadIdx.x;
    if (i >= CW_TOTAL) return;
    int j = i;
    if (j < SZ_WMSG)  { g_wmsg[j]  = __float2bfloat16_rn(Wmsg[j]);  return; } j -= SZ_WMSG;
    if (j < SZ_WNODE) { g_wnode[j] = __float2bfloat16_rn(Wnode[j]); return; } j -= SZ_WNODE;
    if (j < SZ_LC1)   { g_lc1w[j]  = __float2bfloat16_rn(lc1w[j]);  return; } j -= SZ_LC1;
    if (j < SZ_LC2)   { g_lc2w[j]  = __float2bfloat16_rn(lc2w[j]);  return; } j -= SZ_LC2;
    if (j < SZ_WO)    { g_wo[j]    = __float2bfloat16_rn(Wo[j]);    return; } j -= SZ_WO;
    if (j < SZ_WF1)   { g_wf1[j]   = __float2bfloat16_rn(Wf1[j]);   return; } j -= SZ_WF1;
    g_wf2[j] = __float2bfloat16_rn(Wf2[j]);
}

__global__ void pack_qkv_kernel(const float* __restrict__ Wq, const float* __restrict__ Wk,
                                const float* __restrict__ Wv) {
    int i = blockIdx.x * blockDim.x + threadIdx.x;
    if (i >= DG * DG) return;
    int k = i >> 8, n = i & 255;
    g_wqkv[k * 768 + n]       = __float2bfloat16_rn(Wq[i]);
    g_wqkv[k * 768 + 256 + n] = __float2bfloat16_rn(Wk[i]);
    g_wqkv[k * 768 + 512 + n] = __float2bfloat16_rn(Wv[i]);
}

__global__ void embed_kernel(const int* __restrict__ tok, uint4* __restrict__ out, int total16) {
    int i = blockIdx.x * blockDim.x + threadIdx.x;
    if (i >= total16) return;
    int ti = i >> 3;
    int d  = i & 7;
    out[i] = ((const uint4*)g_embf)[tok[ti] * 8 + d];
}

__global__ void zero_kernel(float4* __restrict__ p, int n4) {
    int i = blockIdx.x * blockDim.x + threadIdx.x;
    if (i < n4) p[i] = make_float4(0.f, 0.f, 0.f, 0.f);
}

__device__ __forceinline__ void unpack8(uint4 raw, float* v) {
    const __nv_bfloat162* h = (const __nv_bfloat162*)&raw;
    #pragma unroll
    for (int j = 0; j < 4; j++) {
        v[2*j]   = __bfloat162float(h[j].x);
        v[2*j+1] = __bfloat162float(h[j].y);
    }
}

__global__ void scatter_add_kernel(const int* __restrict__ dst) {
    int i = blockIdx.x * blockDim.x + threadIdx.x;
    if (i >= N_EDGES * FD / 8) return;
    int e = i >> 6, c8 = (i & 63) * 8;
    uint4 raw = *(const uint4*)(g_msg + ((size_t)e << 9) + c8);
    float v[8]; unpack8(raw, v);
    float* base = g_agg + (size_t)dst[e] * FD + c8;
    #pragma unroll
    for (int j = 0; j < 8; j++) atomicAdd(base + j, v[j]);
}

__global__ void edge_gather_kernel(const int* __restrict__ src, const int* __restrict__ dst) {
    int i = blockIdx.x * blockDim.x + threadIdx.x;
    if (i >= N_EDGES * FD / 8) return;
    int e = i >> 6, c8 = (i & 63) * 8;
    uint4 ra = *(const uint4*)(g_h + (size_t)src[e] * FD + c8);
    uint4 rb = *(const uint4*)(g_h + (size_t)dst[e] * FD + c8);
    float a[8], b[8]; unpack8(ra, a); unpack8(rb, b);
    __nv_bfloat162 o[4];
    #pragma unroll
    for (int j = 0; j < 4; j++) {
        o[j].x = __float2bfloat16_rn(a[2*j]   + b[2*j]);
        o[j].y = __float2bfloat16_rn(a[2*j+1] + b[2*j+1]);
    }
    *(uint4*)(g_eh + ((size_t)e << 9) + c8) = *(uint4*)o;
}

// ================= common helpers =================
__device__ __forceinline__ void cp_async16(uint32_t dst, const void* src, bool pred) {
    int sz = pred ? 16 : 0;
    asm volatile("cp.async.cg.shared.global [%0], [%1], 16, %2;\n"
                 :: "r"(dst), "l"(src), "r"(sz));
}
__device__ __forceinline__ void cp_commit() { asm volatile("cp.async.commit_group;\n"); }
__device__ __forceinline__ void cp_wait0()  { asm volatile("cp.async.wait_group 0;\n"); }
__device__ __forceinline__ void cp_wait1()  { asm volatile("cp.async.wait_group 1;\n"); }
__device__ __forceinline__ void cp_wait2()  { asm volatile("cp.async.wait_group 2;\n"); }

__device__ __forceinline__ void mma_bf16(float c[4], const uint32_t a[4], const uint32_t b[2]) {
    asm volatile(
        "mma.sync.aligned.m16n8k16.row.col.f32.bf16.bf16.f32 "
        "{%0,%1,%2,%3}, {%4,%5,%6,%7}, {%8,%9}, {%0,%1,%2,%3};"
        : "+f"(c[0]), "+f"(c[1]), "+f"(c[2]), "+f"(c[3])
        : "r"(a[0]), "r"(a[1]), "r"(a[2]), "r"(a[3]), "r"(b[0]), "r"(b[1]));
}

__device__ __forceinline__ void ldsm_x4(uint32_t& r0, uint32_t& r1, uint32_t& r2, uint32_t& r3,
                                        uint32_t addr) {
    asm volatile("ldmatrix.sync.aligned.m8n8.x4.shared.b16 {%0,%1,%2,%3}, [%4];"
                 : "=r"(r0), "=r"(r1), "=r"(r2), "=r"(r3) : "r"(addr));
}
__device__ __forceinline__ void ldsm_x4_t(uint32_t& r0, uint32_t& r1, uint32_t& r2, uint32_t& r3,
                                          uint32_t addr) {
    asm volatile("ldmatrix.sync.aligned.m8n8.x4.trans.shared.b16 {%0,%1,%2,%3}, [%4];"
                 : "=r"(r0), "=r"(r1), "=r"(r2), "=r"(r3) : "r"(addr));
}

// ================= mma.sync bf16 GEMM (mid-network) =================
// EPI: 0 plain | 1 +biasf[n] | 2 relu(+extraf[m*ld+n]) | 3 relu(+extrab[gidx[m]*ld+n])
//      4 +extrab[m*ld+n] | 5 gelu

#define TBM 128
#define TBN 128
#define TBK 32
#define ASTRH 40
#define BSTRH 136
#define NSTAGE 3
#define A_STAGE_H (TBM * ASTRH)
#define B_STAGE_H (TBK * BSTRH)
#define GEMM_SMEM_BYTES (NSTAGE * (A_STAGE_H + B_STAGE_H) * 2)

template<int EPI>
__global__ void __launch_bounds__(256)
tmma_k(const bf16* __restrict__ A, const bf16* __restrict__ B, void* __restrict__ Cv,
       int M, int N, int K,
       const float* __restrict__ extraf, const bf16* __restrict__ extrab,
       const int* __restrict__ gidx, int ldex) {
    extern __shared__ bf16 smem[];
    bf16* Asm = smem;
    bf16* Bsm = smem + NSTAGE * A_STAGE_H;

    uint32_t aU = (uint32_t)__cvta_generic_to_shared(Asm);
    uint32_t bU = (uint32_t)__cvta_generic_to_shared(Bsm);

    int tid  = threadIdx.x;
    int lane = tid & 31;
    int warp = tid >> 5;
    int wm = warp & 1;
    int wn = warp >> 1;
    int g   = lane >> 2;
    int tig = lane & 3;
    int m0 = blockIdx.y * TBM;
    int n0 = blockIdx.x * TBN;

    float acc[4][4][4] = {};

    auto issue_load = [&](int s, int k0) {
        #pragma unroll
        for (int i = 0; i < 2; i++) {
            int id = tid + i * 256;
            int ar = id >> 2, ak = (id & 3) << 3;
            uint32_t da = aU + (s * A_STAGE_H + ar * ASTRH + ak) * 2;
            cp_async16(da, A + (size_t)(m0 + ar) * K + k0 + ak, true);
            int br = id >> 4, bn = (id & 15) << 3;
            int gn = n0 + bn;
            uint32_t db = bU + (s * B_STAGE_H + br * BSTRH + bn) * 2;
            cp_async16(db, B + (size_t)(k0 + br) * N + gn, gn + 8 <= N);
        }
    };

    int niter = K / TBK;
    issue_load(0, 0);
    cp_commit();
    issue_load(1, TBK);
    cp_commit();

    for (int it = 0; it < niter; it++) {
        if (it == niter - 1) cp_wait0(); else cp_wait1();
        __syncthreads();
        if (it + 2 < niter) {
            issue_load((it + 2) % NSTAGE, (it + 2) * TBK);
            cp_commit();
        }
        int s = it % NSTAGE;
        uint32_t aB = aU + s * A_STAGE_H * 2;
        uint32_t bB = bU + s * B_STAGE_H * 2;
        #pragma unroll
        for (int ks = 0; ks < TBK; ks += 16) {
            uint32_t af[4][4], bfr[4][2];
            #pragma unroll
            for (int mt = 0; mt < 4; mt++) {
                int row = wm * 64 + mt * 16 + (lane & 15);
                uint32_t ad = aB + (row * ASTRH + ks + ((lane >> 4) << 3)) * 2;
                ldsm_x4(af[mt][0], af[mt][1], af[mt][2], af[mt][3], ad);
            }
            #pragma unroll
            for (int bp = 0; bp < 2; bp++) {
                int krow = ks + (lane & 15);
                int ncol = wn * 32 + bp * 16 + ((lane >> 4) << 3);
                uint32_t bd = bB + (krow * BSTRH + ncol) * 2;
                ldsm_x4_t(bfr[2*bp][0], bfr[2*bp][1], bfr[2*bp+1][0], bfr[2*bp+1][1], bd);
            }
            #pragma unroll
            for (int mt = 0; mt < 4; mt++)
                #pragma unroll
                for (int nt = 0; nt < 4; nt++)
                    mma_bf16(acc[mt][nt], af[mt], bfr[nt]);
        }
    }

    bf16* Cb = (bf16*)Cv;

    #pragma unroll
    for (int mt = 0; mt < 4; mt++) {
        #pragma unroll
        for (int half = 0; half < 2; half++) {
            int rib = wm * 64 + mt * 16 + half * 8 + g;
            int r = m0 + rib;
            int ebase = 0;
            if (EPI == 2 || EPI == 4) ebase = r * ldex;
            if (EPI == 3)             ebase = gidx[r] * ldex;

            #pragma unroll
            for (int nt = 0; nt < 4; nt++) {
                int n = n0 + wn * 32 + nt * 8 + 2 * tig;
                float c0 = acc[mt][nt][half * 2 + 0];
                float c1 = acc[mt][nt][half * 2 + 1];
                if (EPI == 1) { c0 += extraf[n]; c1 += extraf[n + 1]; }
                else if (EPI == 2) {
                    c0 = fmaxf(c0 + extraf[ebase + n],     0.0f);
                    c1 = fmaxf(c1 + extraf[ebase + n + 1], 0.0f);
                } else if (EPI == 3) {
                    c0 = fmaxf(c0 + __bfloat162float(extrab[ebase + n]),     0.0f);
                    c1 = fmaxf(c1 + __bfloat162float(extrab[ebase + n + 1]), 0.0f);
                } else if (EPI == 4) {
                    c0 += __bfloat162float(extrab[ebase + n]);
                    c1 += __bfloat162float(extrab[ebase + n + 1]);
                } else if (EPI == 5) {
                    float x = c0;
                    c0 = 0.5f * x * (1.0f + tanhf(0.7978845608028654f * (x + 0.044715f * x * x * x)));
                    x = c1;
                    c1 = 0.5f * x * (1.0f + tanhf(0.7978845608028654f * (x + 0.044715f * x * x * x)));
                }
                if (n + 1 < N) {
                    __nv_bfloat162 p;
                    p.x = __float2bfloat16_rn(c0);
                    p.y = __float2bfloat16_rn(c1);
                    *(__nv_bfloat162*)&Cb[(size_t)r * N + n] = p;
                }
            }
        }
    }
}

// ================= fused persistent LM head (K=64, A-frags in registers) =================
// grid = 128 CTAs (one per 128-row block), 256 threads.
// Pass 1: stream all 79 vocab tiles, online (max, sumexp) in registers.
// Reduce stats (shfl + smem). Pass 2: recompute (identical MMA order), write probs.

#define LMSTR   144                      // smem row stride bytes (16B aligned, conflict-free)
#define LM_AB   (128 * LMSTR)            // A tile bytes = one B stage bytes
#define LM_NTILE 79
#define LM_SMEM_TOT (LM_AB + 3 * LM_AB + 128 * 4 * 8 + 128 * 8)   // 78848

__global__ void __launch_bounds__(256, 1)
lm_fused(const bf16* __restrict__ Ag, float* __restrict__ probs) {
    extern __shared__ char smc[];
    uint32_t aU = (uint32_t)__cvta_generic_to_shared(smc);
    uint32_t bU = aU + LM_AB;
    float2* spart = (float2*)(smc + 4 * LM_AB);      // [128][4]
    float2* sstat = spart + 128 * 4;                 // [128]

    int tid = threadIdx.x;
    int lane = tid & 31, warp = tid >> 5;
    int wm = warp & 1, wn = warp >> 1;
    int g = lane >> 2, tig = lane & 3;
    int m0 = blockIdx.x * 128;

    // load A tile (128 rows x 128 B)
    const char* Ab = (const char*)Ag;
    #pragma unroll
    for (int i = 0; i < 4; i++) {
        int id = tid + i * 256;
        int row = id >> 3, c = (id & 7) << 4;
        cp_async16(aU + row * LMSTR + c, Ab + (size_t)(m0 + row) * 128 + c, true);
    }
    cp_commit();

    auto issue_B = [&](int stage, int t) {
        const char* Bb = (const char*)g_embf;
        #pragma unroll
        for (int i = 0; i < 4; i++) {
            int id = tid + i * 256;
            int row = id >> 3, c = (id & 7) << 4;
            int v = t * 128 + row;
            cp_async16(bU + stage * LM_AB + row * LMSTR + c,
                       Bb + (size_t)v * 128 + c, v < VOCAB);
        }
        cp_commit();
    };

    issue_B(0, 0);
    issue_B(1, 1);
    cp_wait2();            // A arrived
    __syncthreads();

    // preload ALL A fragments (4 ksteps x 4 mt)
    uint32_t af[4][4][4];
    #pragma unroll
    for (int mt = 0; mt < 4; mt++)
        #pragma unroll
        for (int ks = 0; ks < 4; ks++) {
            uint32_t ad = aU + (wm * 64 + mt * 16 + (lane & 15)) * LMSTR
                        + ks * 32 + ((lane >> 4) << 4);
            ldsm_x4(af[mt][ks][0], af[mt][ks][1], af[mt][ks][2], af[mt][ks][3], ad);
        }

    float rm[8], rs[8];
    #pragma unroll
    for (int s = 0; s < 8; s++) { rm[s] = -1e30f; rs[s] = 0.0f; }

    // B ldmatrix addressing (non-trans from [n][k] rows == trans from [k][n])
    int brow = (lane & 7) + ((lane >> 4) << 3);
    int bcol16 = ((lane >> 3) & 1) << 4;

    // ======== PASS 1: stats ========
    for (int t = 0; t < LM_NTILE; t++) {
        if (t == LM_NTILE - 1) cp_wait0(); else cp_wait1();
        __syncthreads();
        if (t + 2 < LM_NTILE) issue_B((t + 2) % 3, t + 2);

        uint32_t bB = bU + (t % 3) * LM_AB;
        float acc[4][4][4] = {};
        #pragma unroll
        for (int ks = 0; ks < 4; ks++) {
            uint32_t bfr[4][2];
            #pragma unroll
            for (int p = 0; p < 2; p++) {
                uint32_t bd = bB + (wn * 32 + p * 16 + brow) * LMSTR + ks * 32 + bcol16;
                ldsm_x4(bfr[2*p][0], bfr[2*p][1], bfr[2*p+1][0], bfr[2*p+1][1], bd);
            }
            #pragma unroll
            for (int mt = 0; mt < 4; mt++)
                #pragma unroll
                for (int nt = 0; nt < 4; nt++)
                    mma_bf16(acc[mt][nt], af[mt][ks], bfr[nt]);
        }

        int nb0 = t * 128 + wn * 32 + 2 * tig;
        #pragma unroll
        for (int mt = 0; mt < 4; mt++)
            #pragma unroll
            for (int half = 0; half < 2; half++) {
                int slot = mt * 2 + half;
                float v[8];
                float bm = -1e30f;
                #pragma unroll
                for (int nt = 0; nt < 4; nt++)
                    #pragma unroll
                    for (int j = 0; j < 2; j++) {
                        int n = nb0 + nt * 8 + j;
                        float x = (n < VOCAB) ? acc[mt][nt][half * 2 + j] : -1e30f;
                        v[nt * 2 + j] = x;
                        bm = fmaxf(bm, x);
                    }
                float nm = fmaxf(rm[slot], bm);
                float add = 0.0f;
                #pragma unroll
                for (int j = 0; j < 8; j++) add += __expf(v[j] - nm);
                rs[slot] = rs[slot] * __expf(rm[slot] - nm) + add;
                rm[slot] = nm;
            }
    }

    // ---- reduce stats: across tig (shfl), then across wn (smem) ----
    #pragma unroll
    for (int slot = 0; slot < 8; slot++) {
        float m = rm[slot], s = rs[slot];
        #pragma unroll
        for (int off = 1; off <= 2; off <<= 1) {
            float om = __shfl_xor_sync(0xffffffffu, m, off);
            float os = __shfl_xor_sync(0xffffffffu, s, off);
            float nm = fmaxf(m, om);
            s = s * __expf(m - nm) + os * __expf(om - nm);
            m = nm;
        }
        int mt = slot >> 1, half = slot & 1;
        int rib = wm * 64 + mt * 16 + half * 8 + g;
        if (tig == 0) spart[rib * 4 + wn] = make_float2(m, s);
    }
    __syncthreads();
    if (tid < 128) {
        float m = -1e30f, s = 0.0f;
        #pragma unroll
        for (int w = 0; w < 4; w++) {
            float2 p = spart[tid * 4 + w];
            float nm = fmaxf(m, p.x);
            s = s * __expf(m - nm) + p.y * __expf(p.x - nm);
            m = nm;
        }
        sstat[tid] = make_float2(m, 1.0f / s);
    }
    __syncthreads();

    // load per-slot stats into registers
    float stm[8], sti[8];
    #pragma unroll
    for (int slot = 0; slot < 8; slot++) {
        int mt = slot >> 1, half = slot & 1;
        int rib = wm * 64 + mt * 16 + half * 8 + g;
        float2 st = sstat[rib];
        stm[slot] = st.x; sti[slot] = st.y;
    }

    // ======== PASS 2: recompute + write probs ========
    issue_B(0, 0);
    issue_B(1, 1);
    for (int t = 0; t < LM_NTILE; t++) {
        if (t == LM_NTILE - 1) cp_wait0(); else cp_wait1();
        __syncthreads();
        if (t + 2 < LM_NTILE) issue_B((t + 2) % 3, t + 2);

        uint32_t bB = bU + (t % 3) * LM_AB;
        float acc[4][4][4] = {};
        #pragma unroll
        for (int ks = 0; ks < 4; ks++) {
            uint32_t bfr[4][2];
            #pragma unroll
            for (int p = 0; p < 2; p++) {
                uint32_t bd = bB + (wn * 32 + p * 16 + brow) * LMSTR + ks * 32 + bcol16;
                ldsm_x4(bfr[2*p][0], bfr[2*p][1], bfr[2*p+1][0], bfr[2*p+1][1], bd);
            }
            #pragma unroll
            for (int mt = 0; mt < 4; mt++)
                #pragma unroll
                for (int nt = 0; nt < 4; nt++)
                    mma_bf16(acc[mt][nt], af[mt][ks], bfr[nt]);
        }

        int nb0 = t * 128 + wn * 32 + 2 * tig;
        #pragma unroll
        for (int mt = 0; mt < 4; mt++)
            #pragma unroll
            for (int half = 0; half < 2; half++) {
                int slot = mt * 2 + half;
                int rib = wm * 64 + mt * 16 + half * 8 + g;
                size_t rowoff = (size_t)(m0 + rib) * VOCAB;
                float m = stm[slot], inv = sti[slot];
                #pragma unroll
                for (int nt = 0; nt < 4; nt++) {
                    int n = nb0 + nt * 8;
                    if (n < VOCAB) {
                        float p0 = __expf(acc[mt][nt][half * 2 + 0] - m) * inv;
                        float p1 = __expf(acc[mt][nt][half * 2 + 1] - m) * inv;
                        *(float2*)&probs[rowoff + n] = make_float2(p0, p1);
                    }
                }
            }
    }
}

// ---------------- attention ----------------
__global__ void __launch_bounds__(256) attention_kernel() {
    __shared__ float qs[8][DG], ks[8][DG], vs[8][DG];
    int b = blockIdx.x;
    int tid = threadIdx.x;
    for (int i = tid; i < 8 * DG; i += 256) {
        int s = i >> 8, c = i & 255;
        size_t off = (size_t)(b * 8 + s) * 768 + c;
        qs[s][c] = __bfloat162float(g_qkv[off]);
        ks[s][c] = __bfloat162float(g_qkv[off + 256]);
        vs[s][c] = __bfloat162float(g_qkv[off + 512]);
    }
    __syncthreads();

    int h  = tid >> 6;
    int qx = (tid >> 3) & 7;
    int kx = tid & 7;
    float att = 0.0f;
    #pragma unroll
    for (int d = 0; d < HD; d++)
        att += qs[qx][h * HD + d] * ks[kx][h * HD + d];
    att *= 0.125f;

    float mx = att;
    mx = fmaxf(mx, __shfl_xor_sync(0xffffffffu, mx, 4));
    mx = fmaxf(mx, __shfl_xor_sync(0xffffffffu, mx, 2));
    mx = fmaxf(mx, __shfl_xor_sync(0xffffffffu, mx, 1));
    float ex = expf(att - mx);
    float sm = ex;
    sm += __shfl_xor_sync(0xffffffffu, sm, 4);
    sm += __shfl_xor_sync(0xffffffffu, sm, 2);
    sm += __shfl_xor_sync(0xffffffffu, sm, 1);
    float a = ex / sm;

    int lane = tid & 31;
    int base = lane & ~7;
    float a_all[8];
    #pragma unroll
    for (int kk = 0; kk < 8; kk++)
        a_all[kk] = __shfl_sync(0xffffffffu, a, base + kk);

    #pragma unroll
    for (int t2 = 0; t2 < 8; t2++) {
        int d = kx * 8 + t2;
        float o = 0.0f;
        #pragma unroll
        for (int kk = 0; kk < 8; kk++)
            o += a_all[kk] * vs[kk][h * HD + d];
        g_ao[(size_t)(b * 8 + qx) * DG + h * HD + d] = __float2bfloat16_rn(o);
    }
}

// ---------------- host launcher ----------------
template<int EPI>
static void launch_one(const bf16* A, const bf16* B, void* C, int M, int N, int K,
                       const float* extraf, const bf16* extrab,
                       const int* gidx, int ldex) {
    static bool attr_done = false;
    if (!attr_done) {
        cudaFuncSetAttribute(tmma_k<EPI>, cudaFuncAttributeMaxDynamicSharedMemorySize,
                             GEMM_SMEM_BYTES);
        attr_done = true;
    }
    dim3 grid((N + TBN - 1) / TBN, M / TBM), blk(256);
    tmma_k<EPI><<<grid, blk, GEMM_SMEM_BYTES>>>(A, B, C, M, N, K, extraf, extrab, gidx, ldex);
}

static void launch_gemm(int epi, const bf16* A, const bf16* B, void* C,
                        int M, int N, int K,
                        const float* extraf = nullptr, const bf16* extrab = nullptr,
                        const int* gidx = nullptr, int ldex = 0) {
    switch (epi) {
        case 0: launch_one<0>(A, B, C, M, N, K, extraf, extrab, gidx, ldex); break;
        case 1: launch_one<1>(A, B, C, M, N, K, extraf, extrab, gidx, ldex); break;
        case 2: launch_one<2>(A, B, C, M, N, K, extraf, extrab, gidx, ldex); break;
        case 3: launch_one<3>(A, B, C, M, N, K, extraf, extrab, gidx, ldex); break;
        case 4: launch_one<4>(A, B, C, M, N, K, extraf, extrab, gidx, ldex); break;
        case 5: launch_one<5>(A, B, C, M, N, K, extraf, extrab, gidx, ldex); break;
    }
}

template <typename T>
static T* sym_addr(const void* sym) {
    void* p = nullptr;
    cudaGetSymbolAddress(&p, sym);
    return (T*)p;
}

extern "C" void kernel_launch(void* const* d_in, const int* in_sizes, int n_in,
                              void* d_out, int out_size) {
    const int*   node_tokens = (const int*)d_in[0];
    const int*   edge_tokens = (const int*)d_in[1];
    const int*   edge_index  = (const int*)d_in[2];
    const void*  mask_rows   = d_in[3];
    const float* emb    = (const float*)d_in[4];
    const float* W_msg  = (const float*)d_in[5];
    const float* W_node = (const float*)d_in[6];
    const float* lc1_w  = (const float*)d_in[7];
    const float* lc1_b  = (const float*)d_in[8];
    const float* lc2_w  = (const float*)d_in[9];
    const float* lc2_b  = (const float*)d_in[10];
    const float* Wq  = (const float*)d_in[11];
    const float* Wk  = (const float*)d_in[12];
    const float* Wv  = (const float*)d_in[13];
    const float* Wo  = (const float*)d_in[14];
    const float* Wf1 = (const float*)d_in[15];
    const float* Wf2 = (const float*)d_in[16];

    float* out = (float*)d_out;
    bool concat = (out_size != ROWS * VOCAB);
    float* labels_out = concat ? out : nullptr;
    float* probs      = concat ? out + ROWS : out;

    const int* src = edge_index;
    const int* dst = edge_index + N_EDGES;

    bf16* px   = sym_addr<bf16>(g_x);
    bf16* pe   = sym_addr<bf16>(g_e);
    bf16* pmsg = sym_addr<bf16>(g_msg);
    float* pagg= sym_addr<float>(g_agg);
    bf16* ph   = sym_addr<bf16>(g_h);
    bf16* peh  = sym_addr<bf16>(g_eh);
    bf16* pzg  = sym_addr<bf16>(g_zg);
    bf16* pqkv = sym_addr<bf16>(g_qkv);
    bf16* pao  = sym_addr<bf16>(g_ao);
    bf16* px1  = sym_addr<bf16>(g_x1);
    bf16* pffn = sym_addr<bf16>(g_ffn);
    bf16* px2  = sym_addr<bf16>(g_x2);
    bf16* py   = sym_addr<bf16>(g_y);
    bf16* pwmsg = sym_addr<bf16>(g_wmsg);
    bf16* pwnode= sym_addr<bf16>(g_wnode);
    bf16* plc1w = sym_addr<bf16>(g_lc1w);
    bf16* plc2w = sym_addr<bf16>(g_lc2w);
    bf16* pwo   = sym_addr<bf16>(g_wo);
    bf16* pwf1  = sym_addr<bf16>(g_wf1);
    bf16* pwf2  = sym_addr<bf16>(g_wf2);
    bf16* pwqkv = sym_addr<bf16>(g_wqkv);
    int*  pmt   = sym_addr<int>(g_mtok);

    // 1. mask dtype detect + labels/masked tokens
    detect_mask_kernel<<<1, 512>>>((const int*)mask_rows);
    mask_kernel<<<(N_EDGES * L_TOK + 255) / 256, 256>>>(edge_tokens, mask_rows, labels_out);

    // 2. conversions + embeddings
    convert_emb_kernel<<<(VOCAB * D_GNN + 255) / 256, 256>>>(emb);
    convert_weights_kernel<<<(CW_TOTAL + 255) / 256, 256>>>(W_msg, W_node, lc1_w, lc2_w,
                                                            Wo, Wf1, Wf2);
    pack_qkv_kernel<<<(DG * DG + 255) / 256, 256>>>(Wq, Wk, Wv);
    embed_kernel<<<(N_NODES * FD / 8 + 255) / 256, 256>>>(node_tokens, (uint4*)px, N_NODES * FD / 8);
    embed_kernel<<<(N_EDGES * FD / 8 + 255) / 256, 256>>>(pmt, (uint4*)pe, N_EDGES * FD / 8);

    // 3. GNN
    launch_gemm(3, pe, pwmsg, pmsg, N_EDGES, FD, FD, nullptr, px, src, FD);
    zero_kernel<<<(N_NODES * FD / 4 + 255) / 256, 256>>>((float4*)pagg, N_NODES * FD / 4);
    scatter_add_kernel<<<(N_EDGES * FD / 8 + 255) / 256, 256>>>(dst);
    launch_gemm(2, px, pwnode, ph, N_NODES, FD, FD, pagg, nullptr, nullptr, FD);
    edge_gather_kernel<<<(N_EDGES * FD / 8 + 255) / 256, 256>>>(src, dst);

    // 4. lc1
    launch_gemm(1, peh, plc1w, pzg, ROWS, DG, D_GNN, lc1_b);

    // 5. transformer
    launch_gemm(0, pzg, pwqkv, pqkv, ROWS, 3 * DG, DG);
    attention_kernel<<<N_EDGES, 256>>>();
    launch_gemm(4, pao, pwo, px1, ROWS, DG, DG, nullptr, pzg, nullptr, DG);
    launch_gemm(5, px1, pwf1, pffn, ROWS, 4 * DG, DG);
    launch_gemm(4, pffn, pwf2, px2, ROWS, DG, 4 * DG, nullptr, px1, nullptr, DG);

    // 6. lc2 + fused persistent LM head (single kernel: stats + softmax write)
    launch_gemm(1, px2, plc2w, py, ROWS, D_GNN, DG, lc2_b);
    {
        static bool lm_attr = false;
        if (!lm_attr) {
            cudaFuncSetAttribute(lm_fused, cudaFuncAttributeMaxDynamicSharedMemorySize,
                                 LM_SMEM_TOT);
            lm_attr = true;
        }
        lm_fused<<<ROWS / 128, 256, LM_SMEM_TOT>>>(py, probs);
    }
}

// round 10
// speedup vs baseline: 1.9320x; 1.0154x over previous
#include <cuda_runtime.h>
#include <cuda_bf16.h>
#include <math.h>
#include <stdint.h>

// ---------------- problem constants ----------------
#define VOCAB   10000
#define D_GNN   64
#define L_TOK   8
#define DG      256
#define NH      4
#define HD      64
#define N_NODES 8192
#define N_EDGES 2048
#define FD      512
#define ROWS    16384

typedef __nv_bfloat16 bf16;

// ---------------- scratch (static device memory) ----------------
__device__ bf16  g_x   [N_NODES * FD];
__device__ bf16  g_e   [N_EDGES * FD];
__device__ bf16  g_msg [N_EDGES * FD];
__device__ float g_agg [N_NODES * FD];
__device__ bf16  g_h   [N_NODES * FD];
__device__ bf16  g_eh  [N_EDGES * FD];
__device__ bf16  g_zg  [ROWS * DG];
__device__ bf16  g_qkv [ROWS * 3 * DG];
__device__ bf16  g_ao  [ROWS * DG];
__device__ bf16  g_x1  [ROWS * DG];
__device__ bf16  g_ffn [ROWS * 4 * DG];
__device__ bf16  g_x2  [ROWS * DG];
__device__ bf16  g_wmsg [FD * FD];
__device__ bf16  g_wnode[FD * FD];
__device__ bf16  g_lc1w [D_GNN * DG];
__device__ bf16  g_lc2w [DG * D_GNN];
__device__ bf16  g_wo   [DG * DG];
__device__ bf16  g_wf1  [DG * 4 * DG];
__device__ bf16  g_wf2  [4 * DG * DG];
__device__ bf16  g_wqkv [DG * 3 * DG];
__device__ bf16  g_embf [VOCAB * D_GNN];
__device__ int   g_mtok[N_EDGES * L_TOK];
__device__ int   g_mask_mode;

// ---------------- mask dtype detection ----------------
__global__ void detect_mask_kernel(const int* __restrict__ mr) {
    __shared__ int notint, notflt;
    if (threadIdx.x == 0) { notint = 0; notflt = 0; }
    __syncthreads();
    int w = mr[threadIdx.x];
    if (w != 0 && w != 1)          atomicExch(&notint, 1);
    if (w != 0 && w != 0x3F800000) atomicExch(&notflt, 1);
    __syncthreads();
    if (threadIdx.x == 0)
        g_mask_mode = notint ? (notflt ? 2 : 1) : 0;
}

__global__ void mask_kernel(const int* __restrict__ etok, const void* __restrict__ maskraw,
                            float* labels_out) {
    int i = blockIdx.x * blockDim.x + threadIdx.x;
    if (i >= N_EDGES * L_TOK) return;
    int e = i >> 3;
    int t = etok[i];
    bool mr;
    int mode = g_mask_mode;
    if (mode == 0)      mr = ((const int*)maskraw)[e] != 0;
    else if (mode == 1) mr = ((const float*)maskraw)[e] != 0.0f;
    else                mr = ((const unsigned char*)maskraw)[e] != 0;
    bool msk = mr && (t >= 4);
    g_mtok[i] = msk ? 4 : t;
    if (labels_out) labels_out[i] = msk ? (float)t : -100.0f;
}

// ---------------- merged prep: all weight conversions + emb + qkv pack ----------------
#define SZ_WMSG  (FD*FD)
#define SZ_WNODE (FD*FD)
#define SZ_LC1   (D_GNN*DG)
#define SZ_LC2   (DG*D_GNN)
#define SZ_WO    (DG*DG)
#define SZ_WF1   (DG*4*DG)
#define SZ_WF2   (4*DG*DG)
#define CW_TOTAL (SZ_WMSG+SZ_WNODE+SZ_LC1+SZ_LC2+SZ_WO+SZ_WF1+SZ_WF2)
#define PREP_TOTAL (CW_TOTAL + VOCAB*D_GNN + DG*DG)

__global__ void prep_all_kernel(const float* Wmsg, const float* Wnode,
                                const float* lc1w, const float* lc2w,
                                const float* Wo, const float* Wf1, const float* Wf2,
                                const float* emb, const float* Wq, const float* Wk,
                                const float* Wv) {
    int i = blockIdx.x * blockDim.x + threadIdx.x;
    if (i >= PREP_TOTAL) return;
    int j = i;
    if (j < SZ_WMSG)  { g_wmsg[j]  = __float2bfloat16_rn(Wmsg[j]);  return; } j -= SZ_WMSG;
    if (j < SZ_WNODE) { g_wnode[j] = __float2bfloat16_rn(Wnode[j]); return; } j -= SZ_WNODE;
    if (j < SZ_LC1)   { g_lc1w[j]  = __float2bfloat16_rn(lc1w[j]);  return; } j -= SZ_LC1;
    if (j < SZ_LC2)   { g_lc2w[j]  = __float2bfloat16_rn(lc2w[j]);  return; } j -= SZ_LC2;
    if (j < SZ_WO)    { g_wo[j]    = __float2bfloat16_rn(Wo[j]);    return; } j -= SZ_WO;
    if (j < SZ_WF1)   { g_wf1[j]   = __float2bfloat16_rn(Wf1[j]);   return; } j -= SZ_WF1;
    if (j < SZ_WF2)   { g_wf2[j]   = __float2bfloat16_rn(Wf2[j]);   return; } j -= SZ_WF2;
    if (j < VOCAB*D_GNN) { g_embf[j] = __float2bfloat16_rn(emb[j]); return; } j -= VOCAB*D_GNN;
    int k = j >> 8, n = j & 255;
    g_wqkv[k * 768 + n]       = __float2bfloat16_rn(Wq[j]);
    g_wqkv[k * 768 + 256 + n] = __float2bfloat16_rn(Wk[j]);
    g_wqkv[k * 768 + 512 + n] = __float2bfloat16_rn(Wv[j]);
}

// merged node+edge embedding gather (16B per thread)
#define N16 (N_NODES * FD / 8)
#define E16 (N_EDGES * FD / 8)
__global__ void embed_all_kernel(const int* __restrict__ ntok) {
    int i = blockIdx.x * blockDim.x + threadIdx.x;
    if (i >= N16 + E16) return;
    const uint4* tab = (const uint4*)g_embf;
    if (i < N16) {
        ((uint4*)g_x)[i] = tab[ntok[i >> 3] * 8 + (i & 7)];
    } else {
        int j = i - N16;
        ((uint4*)g_e)[j] = tab[g_mtok[j >> 3] * 8 + (j & 7)];
    }
}

__global__ void zero_kernel(float4* __restrict__ p, int n4) {
    int i = blockIdx.x * blockDim.x + threadIdx.x;
    if (i < n4) p[i] = make_float4(0.f, 0.f, 0.f, 0.f);
}

__device__ __forceinline__ void unpack8(uint4 raw, float* v) {
    const __nv_bfloat162* h = (const __nv_bfloat162*)&raw;
    #pragma unroll
    for (int j = 0; j < 4; j++) {
        v[2*j]   = __bfloat162float(h[j].x);
        v[2*j+1] = __bfloat162float(h[j].y);
    }
}

__global__ void scatter_add_kernel(const int* __restrict__ dst) {
    int i = blockIdx.x * blockDim.x + threadIdx.x;
    if (i >= N_EDGES * FD / 8) return;
    int e = i >> 6, c8 = (i & 63) * 8;
    uint4 raw = *(const uint4*)(g_msg + ((size_t)e << 9) + c8);
    float v[8]; unpack8(raw, v);
    float* base = g_agg + (size_t)dst[e] * FD + c8;
    #pragma unroll
    for (int j = 0; j < 8; j++) atomicAdd(base + j, v[j]);
}

__global__ void edge_gather_kernel(const int* __restrict__ src, const int* __restrict__ dst) {
    int i = blockIdx.x * blockDim.x + threadIdx.x;
    if (i >= N_EDGES * FD / 8) return;
    int e = i >> 6, c8 = (i & 63) * 8;
    uint4 ra = *(const uint4*)(g_h + (size_t)src[e] * FD + c8);
    uint4 rb = *(const uint4*)(g_h + (size_t)dst[e] * FD + c8);
    float a[8], b[8]; unpack8(ra, a); unpack8(rb, b);
    __nv_bfloat162 o[4];
    #pragma unroll
    for (int j = 0; j < 4; j++) {
        o[j].x = __float2bfloat16_rn(a[2*j]   + b[2*j]);
        o[j].y = __float2bfloat16_rn(a[2*j+1] + b[2*j+1]);
    }
    *(uint4*)(g_eh + ((size_t)e << 9) + c8) = *(uint4*)o;
}

// ================= common helpers =================
__device__ __forceinline__ void cp_async16(uint32_t dst, const void* src, bool pred) {
    int sz = pred ? 16 : 0;
    asm volatile("cp.async.cg.shared.global [%0], [%1], 16, %2;\n"
                 :: "r"(dst), "l"(src), "r"(sz));
}
__device__ __forceinline__ void cp_commit() { asm volatile("cp.async.commit_group;\n"); }
__device__ __forceinline__ void cp_wait0()  { asm volatile("cp.async.wait_group 0;\n"); }
__device__ __forceinline__ void cp_wait1()  { asm volatile("cp.async.wait_group 1;\n"); }

__device__ __forceinline__ void mma_bf16(float c[4], const uint32_t a[4], const uint32_t b[2]) {
    asm volatile(
        "mma.sync.aligned.m16n8k16.row.col.f32.bf16.bf16.f32 "
        "{%0,%1,%2,%3}, {%4,%5,%6,%7}, {%8,%9}, {%0,%1,%2,%3};"
        : "+f"(c[0]), "+f"(c[1]), "+f"(c[2]), "+f"(c[3])
        : "r"(a[0]), "r"(a[1]), "r"(a[2]), "r"(a[3]), "r"(b[0]), "r"(b[1]));
}

__device__ __forceinline__ void ldsm_x4(uint32_t& r0, uint32_t& r1, uint32_t& r2, uint32_t& r3,
                                        uint32_t addr) {
    asm volatile("ldmatrix.sync.aligned.m8n8.x4.shared.b16 {%0,%1,%2,%3}, [%4];"
                 : "=r"(r0), "=r"(r1), "=r"(r2), "=r"(r3) : "r"(addr));
}
__device__ __forceinline__ void ldsm_x4_t(uint32_t& r0, uint32_t& r1, uint32_t& r2, uint32_t& r3,
                                          uint32_t addr) {
    asm volatile("ldmatrix.sync.aligned.m8n8.x4.trans.shared.b16 {%0,%1,%2,%3}, [%4];"
                 : "=r"(r0), "=r"(r1), "=r"(r2), "=r"(r3) : "r"(addr));
}

// ================= mma.sync bf16 GEMM (mid-network) =================
// EPI: 0 plain | 1 +biasf[n] | 2 relu(+extraf[m*ld+n]) | 3 relu(+extrab[gidx[m]*ld+n])
//      4 +extrab[m*ld+n] | 5 gelu

#define TBM 128
#define TBN 128
#define TBK 32
#define ASTRH 40
#define BSTRH 136
#define NSTAGE 3
#define A_STAGE_H (TBM * ASTRH)
#define B_STAGE_H (TBK * BSTRH)
#define GEMM_SMEM_BYTES (NSTAGE * (A_STAGE_H + B_STAGE_H) * 2)

template<int EPI>
__global__ void __launch_bounds__(256)
tmma_k(const bf16* __restrict__ A, const bf16* __restrict__ B, void* __restrict__ Cv,
       int M, int N, int K,
       const float* __restrict__ extraf, const bf16* __restrict__ extrab,
       const int* __restrict__ gidx, int ldex) {
    extern __shared__ bf16 smem[];
    bf16* Asm = smem;
    bf16* Bsm = smem + NSTAGE * A_STAGE_H;

    uint32_t aU = (uint32_t)__cvta_generic_to_shared(Asm);
    uint32_t bU = (uint32_t)__cvta_generic_to_shared(Bsm);

    int tid  = threadIdx.x;
    int lane = tid & 31;
    int warp = tid >> 5;
    int wm = warp & 1;
    int wn = warp >> 1;
    int g   = lane >> 2;
    int tig = lane & 3;
    int m0 = blockIdx.y * TBM;
    int n0 = blockIdx.x * TBN;

    float acc[4][4][4] = {};

    auto issue_load = [&](int s, int k0) {
        #pragma unroll
        for (int i = 0; i < 2; i++) {
            int id = tid + i * 256;
            int ar = id >> 2, ak = (id & 3) << 3;
            uint32_t da = aU + (s * A_STAGE_H + ar * ASTRH + ak) * 2;
            cp_async16(da, A + (size_t)(m0 + ar) * K + k0 + ak, true);
            int br = id >> 4, bn = (id & 15) << 3;
            int gn = n0 + bn;
            uint32_t db = bU + (s * B_STAGE_H + br * BSTRH + bn) * 2;
            cp_async16(db, B + (size_t)(k0 + br) * N + gn, gn + 8 <= N);
        }
    };

    int niter = K / TBK;
    issue_load(0, 0);
    cp_commit();
    issue_load(1, TBK);
    cp_commit();

    for (int it = 0; it < niter; it++) {
        if (it == niter - 1) cp_wait0(); else cp_wait1();
        __syncthreads();
        if (it + 2 < niter) {
            issue_load((it + 2) % NSTAGE, (it + 2) * TBK);
            cp_commit();
        }
        int s = it % NSTAGE;
        uint32_t aB = aU + s * A_STAGE_H * 2;
        uint32_t bB = bU + s * B_STAGE_H * 2;
        #pragma unroll
        for (int ks = 0; ks < TBK; ks += 16) {
            uint32_t af[4][4], bfr[4][2];
            #pragma unroll
            for (int mt = 0; mt < 4; mt++) {
                int row = wm * 64 + mt * 16 + (lane & 15);
                uint32_t ad = aB + (row * ASTRH + ks + ((lane >> 4) << 3)) * 2;
                ldsm_x4(af[mt][0], af[mt][1], af[mt][2], af[mt][3], ad);
            }
            #pragma unroll
            for (int bp = 0; bp < 2; bp++) {
                int krow = ks + (lane & 15);
                int ncol = wn * 32 + bp * 16 + ((lane >> 4) << 3);
                uint32_t bd = bB + (krow * BSTRH + ncol) * 2;
                ldsm_x4_t(bfr[2*bp][0], bfr[2*bp][1], bfr[2*bp+1][0], bfr[2*bp+1][1], bd);
            }
            #pragma unroll
            for (int mt = 0; mt < 4; mt++)
                #pragma unroll
                for (int nt = 0; nt < 4; nt++)
                    mma_bf16(acc[mt][nt], af[mt], bfr[nt]);
        }
    }

    bf16* Cb = (bf16*)Cv;

    #pragma unroll
    for (int mt = 0; mt < 4; mt++) {
        #pragma unroll
        for (int half = 0; half < 2; half++) {
            int rib = wm * 64 + mt * 16 + half * 8 + g;
            int r = m0 + rib;
            int ebase = 0;
            if (EPI == 2 || EPI == 4) ebase = r * ldex;
            if (EPI == 3)             ebase = gidx[r] * ldex;

            #pragma unroll
            for (int nt = 0; nt < 4; nt++) {
                int n = n0 + wn * 32 + nt * 8 + 2 * tig;
                float c0 = acc[mt][nt][half * 2 + 0];
                float c1 = acc[mt][nt][half * 2 + 1];
                if (EPI == 1) { c0 += extraf[n]; c1 += extraf[n + 1]; }
                else if (EPI == 2) {
                    c0 = fmaxf(c0 + extraf[ebase + n],     0.0f);
                    c1 = fmaxf(c1 + extraf[ebase + n + 1], 0.0f);
                } else if (EPI == 3) {
                    c0 = fmaxf(c0 + __bfloat162float(extrab[ebase + n]),     0.0f);
                    c1 = fmaxf(c1 + __bfloat162float(extrab[ebase + n + 1]), 0.0f);
                } else if (EPI == 4) {
                    c0 += __bfloat162float(extrab[ebase + n]);
                    c1 += __bfloat162float(extrab[ebase + n + 1]);
                } else if (EPI == 5) {
                    float x = c0;
                    c0 = 0.5f * x * (1.0f + tanhf(0.7978845608028654f * (x + 0.044715f * x * x * x)));
                    x = c1;
                    c1 = 0.5f * x * (1.0f + tanhf(0.7978845608028654f * (x + 0.044715f * x * x * x)));
                }
                if (n + 1 < N) {
                    __nv_bfloat162 p;
                    p.x = __float2bfloat16_rn(c0);
                    p.y = __float2bfloat16_rn(c1);
                    *(__nv_bfloat162*)&Cb[(size_t)r * N + n] = p;
                }
            }
        }
    }
}

// ================= fused persistent LM head (lc2 + logits + softmax) =================
// grid = 128 CTAs, 256 threads.
// Preamble: y[128,64] = x2[128,256] @ lc2w + b  (into smem A region, bf16)
// Pass 1: stream 79 vocab tiles, online (max,sumexp). Reduce. Pass 2: recompute, write probs.

#define LMSTR   144
#define LM_AB   (128 * LMSTR)
#define LM_NTILE 79
#define LM_X2_OFF  LM_AB                       // preamble x2 tile, stride 528
#define LM_W2_OFF  (LM_AB + 128 * 528)         // preamble lc2w, stride 144
#define LM_STAT_OFF (4 * LM_AB)                // spart/sstat (after B stages)
#define LM_SMEM_TOT (LM_W2_OFF + 256 * 144)    // 122880

__global__ void __launch_bounds__(256, 1)
lm_fused(float* __restrict__ probs, const float* __restrict__ lc2b) {
    extern __shared__ char smc[];
    uint32_t aU = (uint32_t)__cvta_generic_to_shared(smc);
    uint32_t bU = aU + LM_AB;
    float2* spart = (float2*)(smc + LM_STAT_OFF);    // [128][4]
    float2* sstat = spart + 128 * 4;                 // [128]

    int tid = threadIdx.x;
    int lane = tid & 31, warp = tid >> 5;
    int wm = warp & 1, wn = warp >> 1;
    int g = lane >> 2, tig = lane & 3;
    int m0 = blockIdx.x * 128;

    // ---- preamble: load x2 tile + lc2w, compute y into A region ----
    {
        uint32_t xU = aU + LM_X2_OFF;
        uint32_t wU = aU + LM_W2_OFF;
        const char* X2b = (const char*)g_x2;
        #pragma unroll
        for (int i = 0; i < 16; i++) {
            int id = tid + i * 256;
            int row = id >> 5, c = (id & 31) << 4;
            cp_async16(xU + row * 528 + c, X2b + (size_t)(m0 + row) * 512 + c, true);
        }
        const char* W2b = (const char*)g_lc2w;
        #pragma unroll
        for (int i = 0; i < 8; i++) {
            int id = tid + i * 256;
            int row = id >> 3, c = (id & 7) << 4;
            cp_async16(wU + row * 144 + c, W2b + (size_t)row * 128 + c, true);
        }
        cp_commit(); cp_wait0();
        __syncthreads();

        // warp w: rows w*16..+15, all 64 cols
        float yacc[8][4] = {};
        #pragma unroll
        for (int ks = 0; ks < 16; ks++) {
            uint32_t axf[4];
            uint32_t ad = xU + (warp * 16 + (lane & 15)) * 528
                        + (ks * 16 + ((lane >> 4) << 3)) * 2;
            ldsm_x4(axf[0], axf[1], axf[2], axf[3], ad);
            uint32_t bw[8][2];
            #pragma unroll
            for (int p = 0; p < 4; p++) {
                uint32_t bd = wU + (ks * 16 + (lane & 15)) * 144
                            + (p * 16 + ((lane >> 4) << 3)) * 2;
                ldsm_x4_t(bw[2*p][0], bw[2*p][1], bw[2*p+1][0], bw[2*p+1][1], bd);
            }
            #pragma unroll
            for (int nt = 0; nt < 8; nt++)
                mma_bf16(yacc[nt], axf, bw[nt]);
        }
        __syncthreads();   // all reads of x2/lc2w done before A-region writes & B streams

        #pragma unroll
        for (int half = 0; half < 2; half++) {
            int rib = warp * 16 + half * 8 + g;
            #pragma unroll
            for (int nt = 0; nt < 8; nt++) {
                int col = nt * 8 + 2 * tig;
                float v0 = yacc[nt][half * 2 + 0] + lc2b[col];
                float v1 = yacc[nt][half * 2 + 1] + lc2b[col + 1];
                __nv_bfloat162 p;
                p.x = __float2bfloat16_rn(v0);
                p.y = __float2bfloat16_rn(v1);
                *(__nv_bfloat162*)(smc + rib * LMSTR + col * 2) = p;
            }
        }
        __syncthreads();
    }

    auto issue_B = [&](int stage, int t) {
        const char* Bb = (const char*)g_embf;
        #pragma unroll
        for (int i = 0; i < 4; i++) {
            int id = tid + i * 256;
            int row = id >> 3, c = (id & 7) << 4;
            int v = t * 128 + row;
            cp_async16(bU + stage * LM_AB + row * LMSTR + c,
                       Bb + (size_t)v * 128 + c, v < VOCAB);
        }
        cp_commit();
    };

    issue_B(0, 0);
    issue_B(1, 1);

    // preload ALL A fragments (4 ksteps x 4 mt)
    uint32_t af[4][4][4];
    #pragma unroll
    for (int mt = 0; mt < 4; mt++)
        #pragma unroll
        for (int ks = 0; ks < 4; ks++) {
            uint32_t ad = aU + (wm * 64 + mt * 16 + (lane & 15)) * LMSTR
                        + ks * 32 + ((lane >> 4) << 4);
            ldsm_x4(af[mt][ks][0], af[mt][ks][1], af[mt][ks][2], af[mt][ks][3], ad);
        }

    float rm[8], rs[8];
    #pragma unroll
    for (int s = 0; s < 8; s++) { rm[s] = -1e30f; rs[s] = 0.0f; }

    int brow = (lane & 7) + ((lane >> 4) << 3);
    int bcol16 = ((lane >> 3) & 1) << 4;

    // ======== PASS 1: stats ========
    for (int t = 0; t < LM_NTILE; t++) {
        if (t == LM_NTILE - 1) cp_wait0(); else cp_wait1();
        __syncthreads();
        if (t + 2 < LM_NTILE) issue_B((t + 2) % 3, t + 2);

        uint32_t bB = bU + (t % 3) * LM_AB;
        float acc[4][4][4] = {};
        #pragma unroll
        for (int ks = 0; ks < 4; ks++) {
            uint32_t bfr[4][2];
            #pragma unroll
            for (int p = 0; p < 2; p++) {
                uint32_t bd = bB + (wn * 32 + p * 16 + brow) * LMSTR + ks * 32 + bcol16;
                ldsm_x4(bfr[2*p][0], bfr[2*p][1], bfr[2*p+1][0], bfr[2*p+1][1], bd);
            }
            #pragma unroll
            for (int mt = 0; mt < 4; mt++)
                #pragma unroll
                for (int nt = 0; nt < 4; nt++)
                    mma_bf16(acc[mt][nt], af[mt][ks], bfr[nt]);
        }

        int nb0 = t * 128 + wn * 32 + 2 * tig;
        #pragma unroll
        for (int mt = 0; mt < 4; mt++)
            #pragma unroll
            for (int half = 0; half < 2; half++) {
                int slot = mt * 2 + half;
                float v[8];
                float bm = -1e30f;
                #pragma unroll
                for (int nt = 0; nt < 4; nt++)
                    #pragma unroll
                    for (int j = 0; j < 2; j++) {
                        int n = nb0 + nt * 8 + j;
                        float x = (n < VOCAB) ? acc[mt][nt][half * 2 + j] : -1e30f;
                        v[nt * 2 + j] = x;
                        bm = fmaxf(bm, x);
                    }
                float nm = fmaxf(rm[slot], bm);
                float add = 0.0f;
                #pragma unroll
                for (int j = 0; j < 8; j++) add += __expf(v[j] - nm);
                rs[slot] = rs[slot] * __expf(rm[slot] - nm) + add;
                rm[slot] = nm;
            }
    }

    // ---- reduce stats ----
    #pragma unroll
    for (int slot = 0; slot < 8; slot++) {
        float m = rm[slot], s = rs[slot];
        #pragma unroll
        for (int off = 1; off <= 2; off <<= 1) {
            float om = __shfl_xor_sync(0xffffffffu, m, off);
            float os = __shfl_xor_sync(0xffffffffu, s, off);
            float nm = fmaxf(m, om);
            s = s * __expf(m - nm) + os * __expf(om - nm);
            m = nm;
        }
        int mt = slot >> 1, half = slot & 1;
        int rib = wm * 64 + mt * 16 + half * 8 + g;
        if (tig == 0) spart[rib * 4 + wn] = make_float2(m, s);
    }
    __syncthreads();
    if (tid < 128) {
        float m = -1e30f, s = 0.0f;
        #pragma unroll
        for (int w = 0; w < 4; w++) {
            float2 p = spart[tid * 4 + w];
            float nm = fmaxf(m, p.x);
            s = s * __expf(m - nm) + p.y * __expf(p.x - nm);
            m = nm;
        }
        sstat[tid] = make_float2(m, 1.0f / s);
    }
    __syncthreads();

    float stm[8], sti[8];
    #pragma unroll
    for (int slot = 0; slot < 8; slot++) {
        int mt = slot >> 1, half = slot & 1;
        int rib = wm * 64 + mt * 16 + half * 8 + g;
        float2 st = sstat[rib];
        stm[slot] = st.x; sti[slot] = st.y;
    }

    // ======== PASS 2: recompute + write probs (streaming stores) ========
    issue_B(0, 0);
    issue_B(1, 1);
    for (int t = 0; t < LM_NTILE; t++) {
        if (t == LM_NTILE - 1) cp_wait0(); else cp_wait1();
        __syncthreads();
        if (t + 2 < LM_NTILE) issue_B((t + 2) % 3, t + 2);

        uint32_t bB = bU + (t % 3) * LM_AB;
        float acc[4][4][4] = {};
        #pragma unroll
        for (int ks = 0; ks < 4; ks++) {
            uint32_t bfr[4][2];
            #pragma unroll
            for (int p = 0; p < 2; p++) {
                uint32_t bd = bB + (wn * 32 + p * 16 + brow) * LMSTR + ks * 32 + bcol16;
                ldsm_x4(bfr[2*p][0], bfr[2*p][1], bfr[2*p+1][0], bfr[2*p+1][1], bd);
            }
            #pragma unroll
            for (int mt = 0; mt < 4; mt++)
                #pragma unroll
                for (int nt = 0; nt < 4; nt++)
                    mma_bf16(acc[mt][nt], af[mt][ks], bfr[nt]);
        }

        int nb0 = t * 128 + wn * 32 + 2 * tig;
        #pragma unroll
        for (int mt = 0; mt < 4; mt++)
            #pragma unroll
            for (int half = 0; half < 2; half++) {
                int slot = mt * 2 + half;
                int rib = wm * 64 + mt * 16 + half * 8 + g;
                size_t rowoff = (size_t)(m0 + rib) * VOCAB;
                float m = stm[slot], inv = sti[slot];
                #pragma unroll
                for (int nt = 0; nt < 4; nt++) {
                    int n = nb0 + nt * 8;
                    if (n < VOCAB) {
                        float p0 = __expf(acc[mt][nt][half * 2 + 0] - m) * inv;
                        float p1 = __expf(acc[mt][nt][half * 2 + 1] - m) * inv;
                        __stcs((float2*)&probs[rowoff + n], make_float2(p0, p1));
                    }
                }
            }
    }
}

// ---------------- attention ----------------
__global__ void __launch_bounds__(256) attention_kernel() {
    __shared__ float qs[8][DG], ks[8][DG], vs[8][DG];
    int b = blockIdx.x;
    int tid = threadIdx.x;
    for (int i = tid; i < 8 * DG; i += 256) {
        int s = i >> 8, c = i & 255;
        size_t off = (size_t)(b * 8 + s) * 768 + c;
        qs[s][c] = __bfloat162float(g_qkv[off]);
        ks[s][c] = __bfloat162float(g_qkv[off + 256]);
        vs[s][c] = __bfloat162float(g_qkv[off + 512]);
    }
    __syncthreads();

    int h  = tid >> 6;
    int qx = (tid >> 3) & 7;
    int kx = tid & 7;
    float att = 0.0f;
    #pragma unroll
    for (int d = 0; d < HD; d++)
        att += qs[qx][h * HD + d] * ks[kx][h * HD + d];
    att *= 0.125f;

    float mx = att;
    mx = fmaxf(mx, __shfl_xor_sync(0xffffffffu, mx, 4));
    mx = fmaxf(mx, __shfl_xor_sync(0xffffffffu, mx, 2));
    mx = fmaxf(mx, __shfl_xor_sync(0xffffffffu, mx, 1));
    float ex = expf(att - mx);
    float sm = ex;
    sm += __shfl_xor_sync(0xffffffffu, sm, 4);
    sm += __shfl_xor_sync(0xffffffffu, sm, 2);
    sm += __shfl_xor_sync(0xffffffffu, sm, 1);
    float a = ex / sm;

    int lane = tid & 31;
    int base = lane & ~7;
    float a_all[8];
    #pragma unroll
    for (int kk = 0; kk < 8; kk++)
        a_all[kk] = __shfl_sync(0xffffffffu, a, base + kk);

    #pragma unroll
    for (int t2 = 0; t2 < 8; t2++) {
        int d = kx * 8 + t2;
        float o = 0.0f;
        #pragma unroll
        for (int kk = 0; kk < 8; kk++)
            o += a_all[kk] * vs[kk][h * HD + d];
        g_ao[(size_t)(b * 8 + qx) * DG + h * HD + d] = __float2bfloat16_rn(o);
    }
}

// ---------------- host launcher ----------------
template<int EPI>
static void launch_one(const bf16* A, const bf16* B, void* C, int M, int N, int K,
                       const float* extraf, const bf16* extrab,
                       const int* gidx, int ldex) {
    static bool attr_done = false;
    if (!attr_done) {
        cudaFuncSetAttribute(tmma_k<EPI>, cudaFuncAttributeMaxDynamicSharedMemorySize,
                             GEMM_SMEM_BYTES);
        attr_done = true;
    }
    dim3 grid((N + TBN - 1) / TBN, M / TBM), blk(256);
    tmma_k<EPI><<<grid, blk, GEMM_SMEM_BYTES>>>(A, B, C, M, N, K, extraf, extrab, gidx, ldex);
}

static void launch_gemm(int epi, const bf16* A, const bf16* B, void* C,
                        int M, int N, int K,
                        const float* extraf = nullptr, const bf16* extrab = nullptr,
                        const int* gidx = nullptr, int ldex = 0) {
    switch (epi) {
        case 0: launch_one<0>(A, B, C, M, N, K, extraf, extrab, gidx, ldex); break;
        case 1: launch_one<1>(A, B, C, M, N, K, extraf, extrab, gidx, ldex); break;
        case 2: launch_one<2>(A, B, C, M, N, K, extraf, extrab, gidx, ldex); break;
        case 3: launch_one<3>(A, B, C, M, N, K, extraf, extrab, gidx, ldex); break;
        case 4: launch_one<4>(A, B, C, M, N, K, extraf, extrab, gidx, ldex); break;
        case 5: launch_one<5>(A, B, C, M, N, K, extraf, extrab, gidx, ldex); break;
    }
}

template <typename T>
static T* sym_addr(const void* sym) {
    void* p = nullptr;
    cudaGetSymbolAddress(&p, sym);
    return (T*)p;
}

extern "C" void kernel_launch(void* const* d_in, const int* in_sizes, int n_in,
                              void* d_out, int out_size) {
    const int*   node_tokens = (const int*)d_in[0];
    const int*   edge_tokens = (const int*)d_in[1];
    const int*   edge_index  = (const int*)d_in[2];
    const void*  mask_rows   = d_in[3];
    const float* emb    = (const float*)d_in[4];
    const float* W_msg  = (const float*)d_in[5];
    const float* W_node = (const float*)d_in[6];
    const float* lc1_w  = (const float*)d_in[7];
    const float* lc1_b  = (const float*)d_in[8];
    const float* lc2_w  = (const float*)d_in[9];
    const float* lc2_b  = (const float*)d_in[10];
    const float* Wq  = (const float*)d_in[11];
    const float* Wk  = (const float*)d_in[12];
    const float* Wv  = (const float*)d_in[13];
    const float* Wo  = (const float*)d_in[14];
    const float* Wf1 = (const float*)d_in[15];
    const float* Wf2 = (const float*)d_in[16];

    float* out = (float*)d_out;
    bool concat = (out_size != ROWS * VOCAB);
    float* labels_out = concat ? out : nullptr;
    float* probs      = concat ? out + ROWS : out;

    const int* src = edge_index;
    const int* dst = edge_index + N_EDGES;

    bf16* px   = sym_addr<bf16>(g_x);
    bf16* pe   = sym_addr<bf16>(g_e);
    bf16* pmsg = sym_addr<bf16>(g_msg);
    float* pagg= sym_addr<float>(g_agg);
    bf16* ph   = sym_addr<bf16>(g_h);
    bf16* peh  = sym_addr<bf16>(g_eh);
    bf16* pzg  = sym_addr<bf16>(g_zg);
    bf16* pqkv = sym_addr<bf16>(g_qkv);
    bf16* pao  = sym_addr<bf16>(g_ao);
    bf16* px1  = sym_addr<bf16>(g_x1);
    bf16* pffn = sym_addr<bf16>(g_ffn);
    bf16* px2  = sym_addr<bf16>(g_x2);
    bf16* pwmsg = sym_addr<bf16>(g_wmsg);
    bf16* pwnode= sym_addr<bf16>(g_wnode);
    bf16* plc1w = sym_addr<bf16>(g_lc1w);
    bf16* pwo   = sym_addr<bf16>(g_wo);
    bf16* pwf1  = sym_addr<bf16>(g_wf1);
    bf16* pwf2  = sym_addr<bf16>(g_wf2);
    bf16* pwqkv = sym_addr<bf16>(g_wqkv);

    // 1. mask dtype detect + labels/masked tokens
    detect_mask_kernel<<<1, 512>>>((const int*)mask_rows);
    mask_kernel<<<(N_EDGES * L_TOK + 255) / 256, 256>>>(edge_tokens, mask_rows, labels_out);

    // 2. merged prep (all conversions) + merged embeddings
    prep_all_kernel<<<(PREP_TOTAL + 255) / 256, 256>>>(W_msg, W_node, lc1_w, lc2_w,
                                                       Wo, Wf1, Wf2, emb, Wq, Wk, Wv);
    embed_all_kernel<<<(N16 + E16 + 255) / 256, 256>>>(node_tokens);

    // 3. GNN
    launch_gemm(3, pe, pwmsg, pmsg, N_EDGES, FD, FD, nullptr, px, src, FD);
    zero_kernel<<<(N_NODES * FD / 4 + 255) / 256, 256>>>((float4*)pagg, N_NODES * FD / 4);
    scatter_add_kernel<<<(N_EDGES * FD / 8 + 255) / 256, 256>>>(dst);
    launch_gemm(2, px, pwnode, ph, N_NODES, FD, FD, pagg, nullptr, nullptr, FD);
    edge_gather_kernel<<<(N_EDGES * FD / 8 + 255) / 256, 256>>>(src, dst);

    // 4. lc1
    launch_gemm(1, peh, plc1w, pzg, ROWS, DG, D_GNN, lc1_b);

    // 5. transformer
    launch_gemm(0, pzg, pwqkv, pqkv, ROWS, 3 * DG, DG);
    attention_kernel<<<N_EDGES, 256>>>();
    launch_gemm(4, pao, pwo, px1, ROWS, DG, DG, nullptr, pzg, nullptr, DG);
    launch_gemm(5, px1, pwf1, pffn, ROWS, 4 * DG, DG);
    launch_gemm(4, pffn, pwf2, px2, ROWS, DG, 4 * DG, nullptr, px1, nullptr, DG);

    // 6. fused LM head (lc2 + logits + softmax, single persistent kernel)
    {
        static bool lm_attr = false;
        if (!lm_attr) {
            cudaFuncSetAttribute(lm_fused, cudaFuncAttributeMaxDynamicSharedMemorySize,
                                 LM_SMEM_TOT);
            lm_attr = true;
        }
        lm_fused<<<ROWS / 128, 256, LM_SMEM_TOT>>>(probs, lc2_b);
    }
}